// round 5
// baseline (speedup 1.0000x reference)
#include <cuda_runtime.h>
#include <math.h>
#include <stdint.h>

// ---------------- problem constants ----------------
constexpr int B_   = 32;
constexpr int C_   = 256;
constexpr int N_   = 1024;
constexpr int C3_  = 768;
constexpr int MTOT = B_ * N_;   // 32768

// ---------------- scratch ----------------
__device__ float g_mean[C_];
__device__ float g_rstd[C_];
__device__ float g_t  [(size_t)MTOT * C_];    // [B,N,C]   (tf32-rounded)
__device__ float g_kqv[(size_t)MTOT * C3_];   // [B,N,3C]  (tf32-rounded)
__device__ float g_s  [(size_t)B_ * N_ * N_]; // [B,N,N]   (scores / probs)
__device__ float g_vt [(size_t)B_ * C_ * N_]; // [B,C,N]   v transposed
__device__ float g_o  [(size_t)MTOT * C_];    // [B,N,C]   (tf32-rounded)
__device__ float g_po [(size_t)MTOT * C_];    // [B,N,C]

// ---------------- small PTX helpers ----------------
__device__ __forceinline__ uint32_t smem_u32(const void* p) {
    return (uint32_t)__cvta_generic_to_shared(p);
}
__device__ __forceinline__ float round_tf32(float f) {
    uint32_t r;
    asm("cvt.rna.tf32.f32 %0, %1;" : "=r"(r) : "f"(f));
    return __uint_as_float(r);
}
__device__ __forceinline__ void mma_tf32(float c[4], const uint32_t a[4], const uint32_t b[2]) {
    asm volatile(
        "mma.sync.aligned.m16n8k8.row.col.f32.tf32.tf32.f32 "
        "{%0,%1,%2,%3}, {%4,%5,%6,%7}, {%8,%9}, {%0,%1,%2,%3};"
        : "+f"(c[0]), "+f"(c[1]), "+f"(c[2]), "+f"(c[3])
        : "r"(a[0]), "r"(a[1]), "r"(a[2]), "r"(a[3]), "r"(b[0]), "r"(b[1]));
}
#define LDSM_X4(r0, r1, r2, r3, addr) \
    asm volatile("ldmatrix.sync.aligned.m8n8.x4.shared.b16 {%0,%1,%2,%3}, [%4];" \
        : "=r"(r0), "=r"(r1), "=r"(r2), "=r"(r3) : "r"(addr))
#define CP_ASYNC16(dst, src) \
    asm volatile("cp.async.cg.shared.global [%0], [%1], 16;" :: "r"(dst), "l"(src))
#define CP_ASYNC_COMMIT() asm volatile("cp.async.commit_group;" ::: "memory")
#define CP_ASYNC_WAIT(n)  asm volatile("cp.async.wait_group %0;" :: "n"(n) : "memory")

// ---------------- tf32 tensor-core GEMM: C = alpha * A * B^T (+bias) -------
// A [M,K] row-major (lda), B [N,K] row-major (ldb); inputs tf32-rounded fp32.
// CTA tile 128x128, K-chunk 32, 256 threads = 2(M) x 4(N) warps,
// warp tile 64x32 -> 4x4 m16n8k8 MMAs per k8-step. 2-stage cp.async pipe.
// Fragments via ldmatrix.x4 (tf32 fragment == b16 16x16 tile, bit-exact).
constexpr int ROW_F       = 36;                  // padded row stride (floats)
constexpr int TILE_FLOATS = 128 * ROW_F;         // 4608 floats per operand tile
constexpr int TILE_BYTES  = TILE_FLOATS * 4;
constexpr int STAGE_BYTES = 2 * TILE_BYTES;      // A + B
constexpr int SMEM_DYN    = 2 * STAGE_BYTES;     // 73728 B

template <bool BIAS>
__global__ __launch_bounds__(256, 2)
void tc_gemm(const float* __restrict__ A, const float* __restrict__ Bm,
             const float* __restrict__ bias, float* __restrict__ Cm,
             int K, int lda, int ldb, int ldc,
             long sA, long sB, long sC, float alpha, bool round_out) {
    extern __shared__ float sm[];

    const int tid  = threadIdx.x;
    const int lane = tid & 31;
    const int warp = tid >> 5;
    const int wm   = warp & 1;          // 0..1  (M)
    const int wn   = warp >> 1;         // 0..3  (N)
    const int g    = lane >> 2;         // 0..7
    const int q    = lane & 3;          // 0..3

    const int m0 = blockIdx.y * 128;
    const int n0 = blockIdx.x * 128;
    const float* Ab = A  + (size_t)blockIdx.z * sA;
    const float* Bb = Bm + (size_t)blockIdx.z * sB;
    float*       Cb = Cm + (size_t)blockIdx.z * sC;

    const uint32_t smb = smem_u32(sm);

    // per-lane ldmatrix base offsets (bytes), k8/tm/tnp/stage added in loop
    // A (16x8 b32 frag as 16x16 b16): lanes 0-15 rows, lanes 16-31 rows +16B
    const uint32_t a_lo =
        (uint32_t)((wm * 64 + (lane & 15)) * ROW_F * 4 + (lane >> 4) * 16);
    // B (two n8k8 frags per ldmatrix): row = wn*32 + tnp*16 + ((lane>>4)&1)*8 + (lane&7),
    // +16B when (lane>>3)&1
    const uint32_t b_lo =
        (uint32_t)((wn * 32 + ((lane >> 4) & 1) * 8 + (lane & 7)) * ROW_F * 4 +
                   ((lane >> 3) & 1) * 16);

    auto load_stage = [&](int slot, int kc) {
        const uint32_t abase = smb + slot * STAGE_BYTES;
        const uint32_t bbase = abase + TILE_BYTES;
        const float* Asrc = Ab + (size_t)m0 * lda + kc * 32;
        const float* Bsrc = Bb + (size_t)n0 * ldb + kc * 32;
        #pragma unroll
        for (int j = 0; j < 4; j++) {
            int i   = tid + j * 256;
            int row = i >> 3;
            int kg  = i & 7;
            uint32_t off = (uint32_t)(row * ROW_F * 4 + kg * 16);
            CP_ASYNC16(abase + off, Asrc + (size_t)row * lda + kg * 4);
            CP_ASYNC16(bbase + off, Bsrc + (size_t)row * ldb + kg * 4);
        }
        CP_ASYNC_COMMIT();
    };

    float acc[4][4][4] = {};
    const int nk = K >> 5;

    load_stage(0, 0);

    for (int ks = 0; ks < nk; ks++) {
        if (ks + 1 < nk) load_stage((ks + 1) & 1, ks + 1);
        else             CP_ASYNC_COMMIT();
        CP_ASYNC_WAIT(1);                 // stage ks resident
        __syncthreads();

        const uint32_t abase = smb + (ks & 1) * STAGE_BYTES;
        const uint32_t bbase = abase + TILE_BYTES;

        #pragma unroll
        for (int k8 = 0; k8 < 32; k8 += 8) {
            uint32_t af[4][4], bf[4][2];
            #pragma unroll
            for (int tm = 0; tm < 4; tm++) {
                LDSM_X4(af[tm][0], af[tm][1], af[tm][2], af[tm][3],
                        abase + a_lo + (uint32_t)(tm * 16 * ROW_F * 4 + k8 * 4));
            }
            #pragma unroll
            for (int tnp = 0; tnp < 2; tnp++) {
                LDSM_X4(bf[2 * tnp][0], bf[2 * tnp][1], bf[2 * tnp + 1][0], bf[2 * tnp + 1][1],
                        bbase + b_lo + (uint32_t)(tnp * 16 * ROW_F * 4 + k8 * 4));
            }
            #pragma unroll
            for (int tm = 0; tm < 4; tm++)
                #pragma unroll
                for (int tn = 0; tn < 4; tn++)
                    mma_tf32(acc[tm][tn], af[tm], bf[tn]);
        }
        __syncthreads();
    }

    // epilogue: (c0,c1)=row g, (c2,c3)=row g+8; cols 2q, 2q+1
    #pragma unroll
    for (int tm = 0; tm < 4; tm++) {
        const int row = m0 + wm * 64 + tm * 16 + g;
        #pragma unroll
        for (int tn = 0; tn < 4; tn++) {
            const int col = n0 + wn * 32 + tn * 8 + 2 * q;
            float b0 = 0.f, b1 = 0.f;
            if (BIAS) { b0 = __ldg(&bias[col]); b1 = __ldg(&bias[col + 1]); }
            float2 v0, v1;
            v0.x = acc[tm][tn][0] * alpha + b0;
            v0.y = acc[tm][tn][1] * alpha + b1;
            v1.x = acc[tm][tn][2] * alpha + b0;
            v1.y = acc[tm][tn][3] * alpha + b1;
            if (round_out) {
                v0.x = round_tf32(v0.x); v0.y = round_tf32(v0.y);
                v1.x = round_tf32(v1.x); v1.y = round_tf32(v1.y);
            }
            *reinterpret_cast<float2*>(&Cb[(size_t)row * ldc + col])       = v0;
            *reinterpret_cast<float2*>(&Cb[(size_t)(row + 8) * ldc + col]) = v1;
        }
    }
}

// ---------------- BN stats ----------------
__global__ void bn_stats_kernel(const float* __restrict__ x) {
    const int c = blockIdx.x, tid = threadIdx.x;
    float s = 0.f, ss = 0.f;
    for (int i = tid; i < B_ * N_; i += 256) {
        int b = i >> 10, p = i & 1023;
        float v = x[(size_t)b * C_ * N_ + (size_t)c * N_ + p];
        s += v; ss += v * v;
    }
    __shared__ float sh1[256], sh2[256];
    sh1[tid] = s; sh2[tid] = ss;
    __syncthreads();
    for (int k = 128; k > 0; k >>= 1) {
        if (tid < k) { sh1[tid] += sh1[tid + k]; sh2[tid] += sh2[tid + k]; }
        __syncthreads();
    }
    if (tid == 0) {
        const float inv_n = 1.0f / (float)(B_ * N_);
        float mean = sh1[0] * inv_n;
        float var  = sh2[0] * inv_n - mean * mean;
        g_mean[c] = mean;
        g_rstd[c] = rsqrtf(var + 1e-5f);
    }
}

// ------- BN apply + transpose [B,C,N] -> [B,N,C], tf32-rounded -----------
__global__ void bn_apply_transpose_kernel(const float* __restrict__ x,
                                          const float* __restrict__ gamma,
                                          const float* __restrict__ beta) {
    __shared__ float sh[32][33];
    const int b = blockIdx.z, c0 = blockIdx.y * 32, n0 = blockIdx.x * 32;
    const int tx = threadIdx.x, ty = threadIdx.y;
    const int c = c0 + ty;
    float v = x[(size_t)b * C_ * N_ + (size_t)c * N_ + (n0 + tx)];
    v = (v - g_mean[c]) * g_rstd[c] * gamma[c] + beta[c];
    sh[ty][tx] = round_tf32(v);
    __syncthreads();
    g_t[((size_t)b * N_ + (n0 + ty)) * C_ + (c0 + tx)] = sh[tx][ty];
}

// ---------------- V transpose: kqv[:, :, 512:768] -> vt [B,C,N] ----------
__global__ void v_transpose_kernel() {
    __shared__ float sh[32][33];
    const int b = blockIdx.z, c0 = blockIdx.y * 32, n0 = blockIdx.x * 32;
    const int tx = threadIdx.x, ty = threadIdx.y;
    sh[ty][tx] = g_kqv[((size_t)b * N_ + (n0 + ty)) * C3_ + 512 + c0 + tx];
    __syncthreads();
    g_vt[((size_t)b * C_ + (c0 + ty)) * N_ + (n0 + tx)] = sh[tx][ty];
}

// ---------------- softmax over rows of 1024 (float4, warp-shuffle) --------
__global__ void softmax_kernel(float* __restrict__ s) {
    const size_t row = blockIdx.x;
    float4* p4 = reinterpret_cast<float4*>(s + row * (size_t)N_);
    const int tid  = threadIdx.x;     // 256 threads, exactly one float4 each
    const int lane = tid & 31;
    const int wid  = tid >> 5;
    __shared__ float sh[8];

    float4 v = p4[tid];
    float mx = fmaxf(fmaxf(v.x, v.y), fmaxf(v.z, v.w));
    #pragma unroll
    for (int o = 16; o > 0; o >>= 1) mx = fmaxf(mx, __shfl_xor_sync(~0u, mx, o));
    if (lane == 0) sh[wid] = mx;
    __syncthreads();
    mx = sh[0];
    #pragma unroll
    for (int w = 1; w < 8; w++) mx = fmaxf(mx, sh[w]);

    v.x = __expf(v.x - mx); v.y = __expf(v.y - mx);
    v.z = __expf(v.z - mx); v.w = __expf(v.w - mx);
    float sum = v.x + v.y + v.z + v.w;
    #pragma unroll
    for (int o = 16; o > 0; o >>= 1) sum += __shfl_xor_sync(~0u, sum, o);
    __syncthreads();
    if (lane == 0) sh[wid] = sum;
    __syncthreads();
    sum = sh[0];
    #pragma unroll
    for (int w = 1; w < 8; w++) sum += sh[w];
    const float inv = 1.0f / sum;

    v.x = round_tf32(v.x * inv); v.y = round_tf32(v.y * inv);
    v.z = round_tf32(v.z * inv); v.w = round_tf32(v.w * inv);
    p4[tid] = v;
}

// ---------------- final: transpose back + residual ----------------
__global__ void epilogue_kernel(const float* __restrict__ x, float* __restrict__ out) {
    __shared__ float sh[32][33];
    const int b = blockIdx.z, c0 = blockIdx.y * 32, n0 = blockIdx.x * 32;
    const int tx = threadIdx.x, ty = threadIdx.y;
    sh[ty][tx] = g_po[((size_t)b * N_ + (n0 + ty)) * C_ + (c0 + tx)];
    __syncthreads();
    size_t idx = (size_t)b * C_ * N_ + (size_t)(c0 + ty) * N_ + (n0 + tx);
    out[idx] = sh[tx][ty] + x[idx];
}

// ---------------- launch ----------------
extern "C" void kernel_launch(void* const* d_in, const int* in_sizes, int n_in,
                              void* d_out, int out_size) {
    const float* x      = (const float*)d_in[0];
    const float* gamma  = (const float*)d_in[1];
    const float* beta   = (const float*)d_in[2];
    const float* W_kqv  = (const float*)d_in[3];
    const float* b_kqv  = (const float*)d_in[4];
    const float* W_proj = (const float*)d_in[5];
    const float* b_proj = (const float*)d_in[6];
    float* out = (float*)d_out;

    cudaFuncSetAttribute(tc_gemm<true >, cudaFuncAttributeMaxDynamicSharedMemorySize, SMEM_DYN);
    cudaFuncSetAttribute(tc_gemm<false>, cudaFuncAttributeMaxDynamicSharedMemorySize, SMEM_DYN);

    void *pt, *pkqv, *ps, *pvt, *po, *ppo;
    cudaGetSymbolAddress(&pt,   g_t);
    cudaGetSymbolAddress(&pkqv, g_kqv);
    cudaGetSymbolAddress(&ps,   g_s);
    cudaGetSymbolAddress(&pvt,  g_vt);
    cudaGetSymbolAddress(&po,   g_o);
    cudaGetSymbolAddress(&ppo,  g_po);
    float* t   = (float*)pt;
    float* kqv = (float*)pkqv;
    float* s   = (float*)ps;
    float* vt  = (float*)pvt;
    float* o   = (float*)po;
    float* po_ = (float*)ppo;

    bn_stats_kernel<<<C_, 256>>>(x);
    bn_apply_transpose_kernel<<<dim3(N_ / 32, C_ / 32, B_), dim3(32, 32)>>>(x, gamma, beta);

    // kqv = t @ W_kqv^T + b_kqv (outputs tf32-rounded)
    tc_gemm<true><<<dim3(C3_ / 128, MTOT / 128, 1), 256, SMEM_DYN>>>(
        t, W_kqv, b_kqv, kqv, C_, C_, C_, C3_, 0L, 0L, 0L, 1.0f, true);

    // s = q @ k^T / 16 per batch
    tc_gemm<false><<<dim3(N_ / 128, N_ / 128, B_), 256, SMEM_DYN>>>(
        kqv, kqv + 256, nullptr, s, C_, C3_, C3_, N_,
        (long)N_ * C3_, (long)N_ * C3_, (long)N_ * N_, 0.0625f, false);

    softmax_kernel<<<B_ * N_, 256>>>(s);

    v_transpose_kernel<<<dim3(N_ / 32, C_ / 32, B_), dim3(32, 32)>>>();

    // o = attn @ v : A = s [1024,1024], B = vt [256,1024] (BT), per batch
    tc_gemm<false><<<dim3(C_ / 128, N_ / 128, B_), 256, SMEM_DYN>>>(
        s, vt, nullptr, o, N_, N_, N_, C_,
        (long)N_ * N_, (long)C_ * N_, (long)N_ * C_, 1.0f, true);

    // po = o @ W_proj^T + b_proj
    tc_gemm<true><<<dim3(C_ / 128, MTOT / 128, 1), 256, SMEM_DYN>>>(
        o, W_proj, b_proj, po_, C_, C_, C_, C_, 0L, 0L, 0L, 1.0f, false);

    epilogue_kernel<<<dim3(N_ / 32, C_ / 32, B_), dim3(32, 32)>>>(x, out);
}

// round 6
// speedup vs baseline: 1.0526x; 1.0526x over previous
#include <cuda_runtime.h>
#include <math.h>
#include <stdint.h>

// ---------------- problem constants ----------------
constexpr int B_   = 32;
constexpr int C_   = 256;
constexpr int N_   = 1024;
constexpr int C3_  = 768;
constexpr int MTOT = B_ * N_;   // 32768

// ---------------- scratch ----------------
__device__ float g_mean[C_];
__device__ float g_rstd[C_];
__device__ float g_t  [(size_t)MTOT * C_];    // [B,N,C]   (tf32-rounded)
__device__ float g_kqv[(size_t)MTOT * C3_];   // [B,N,3C]  (tf32-rounded)
__device__ float g_s  [(size_t)B_ * N_ * N_]; // [B,N,N]   (scores / probs)
__device__ float g_vt [(size_t)B_ * C_ * N_]; // [B,C,N]   v transposed
__device__ float g_o  [(size_t)MTOT * C_];    // [B,N,C]   (tf32-rounded)

// ---------------- small PTX helpers ----------------
__device__ __forceinline__ uint32_t smem_u32(const void* p) {
    return (uint32_t)__cvta_generic_to_shared(p);
}
__device__ __forceinline__ float round_tf32(float f) {
    uint32_t r;
    asm("cvt.rna.tf32.f32 %0, %1;" : "=r"(r) : "f"(f));
    return __uint_as_float(r);
}
__device__ __forceinline__ void mma_tf32(float c[4], const uint32_t a[4], const uint32_t b[2]) {
    asm volatile(
        "mma.sync.aligned.m16n8k8.row.col.f32.tf32.tf32.f32 "
        "{%0,%1,%2,%3}, {%4,%5,%6,%7}, {%8,%9}, {%0,%1,%2,%3};"
        : "+f"(c[0]), "+f"(c[1]), "+f"(c[2]), "+f"(c[3])
        : "r"(a[0]), "r"(a[1]), "r"(a[2]), "r"(a[3]), "r"(b[0]), "r"(b[1]));
}
#define LDSM_X4(r0, r1, r2, r3, addr) \
    asm volatile("ldmatrix.sync.aligned.m8n8.x4.shared.b16 {%0,%1,%2,%3}, [%4];" \
        : "=r"(r0), "=r"(r1), "=r"(r2), "=r"(r3) : "r"(addr))
#define CP_ASYNC16(dst, src) \
    asm volatile("cp.async.cg.shared.global [%0], [%1], 16;" :: "r"(dst), "l"(src))
#define CP_ASYNC_COMMIT() asm volatile("cp.async.commit_group;" ::: "memory")
#define CP_ASYNC_WAIT(n)  asm volatile("cp.async.wait_group %0;" :: "n"(n) : "memory")

// ---------------- tf32 tensor-core GEMM: C = alpha * A * B^T (+bias) -------
// A [M,K] row-major (lda), B [N,K] row-major (ldb); inputs tf32-rounded fp32.
// CTA tile 128x128, K-chunk 32, 256 threads = 2(M) x 4(N) warps,
// warp tile 64x32 -> 4x4 m16n8k8 MMAs per k8-step.
// 3-stage cp.async pipeline, prefetch distance 2, ONE barrier per chunk.
// TRANSOUT: write out[b, c, n] = acc^T + bias + resid (proj fusion).
constexpr int ROW_F       = 36;                  // padded row stride (floats)
constexpr int TILE_FLOATS = 128 * ROW_F;         // 4608 floats per operand tile
constexpr int TILE_BYTES  = TILE_FLOATS * 4;
constexpr int STAGE_BYTES = 2 * TILE_BYTES;      // A + B = 36864
constexpr int SMEM_DYN    = 3 * STAGE_BYTES;     // 110592 B (2 CTAs/SM fit)

template <bool BIAS, bool TRANSOUT>
__global__ __launch_bounds__(256, 2)
void tc_gemm(const float* __restrict__ A, const float* __restrict__ Bm,
             const float* __restrict__ bias, float* __restrict__ Cm,
             const float* __restrict__ resid,
             int K, int lda, int ldb, int ldc,
             long sA, long sB, long sC, float alpha, bool round_out) {
    extern __shared__ float sm[];

    const int tid  = threadIdx.x;
    const int lane = tid & 31;
    const int warp = tid >> 5;
    const int wm   = warp & 1;          // 0..1  (M)
    const int wn   = warp >> 1;         // 0..3  (N)
    const int g    = lane >> 2;         // 0..7
    const int q    = lane & 3;          // 0..3

    const int m0 = blockIdx.y * 128;
    const int n0 = blockIdx.x * 128;
    const float* Ab = A  + (size_t)blockIdx.z * sA;
    const float* Bb = Bm + (size_t)blockIdx.z * sB;
    float*       Cb = Cm + (size_t)blockIdx.z * sC;

    const uint32_t smb = smem_u32(sm);

    // per-lane ldmatrix base offsets (bytes)
    const uint32_t a_lo =
        (uint32_t)((wm * 64 + (lane & 15)) * ROW_F * 4 + (lane >> 4) * 16);
    const uint32_t b_lo =
        (uint32_t)((wn * 32 + ((lane >> 4) & 1) * 8 + (lane & 7)) * ROW_F * 4 +
                   ((lane >> 3) & 1) * 16);

    auto load_stage = [&](int slot, int kc) {
        const uint32_t abase = smb + slot * STAGE_BYTES;
        const uint32_t bbase = abase + TILE_BYTES;
        const float* Asrc = Ab + (size_t)m0 * lda + kc * 32;
        const float* Bsrc = Bb + (size_t)n0 * ldb + kc * 32;
        #pragma unroll
        for (int j = 0; j < 4; j++) {
            int i   = tid + j * 256;
            int row = i >> 3;
            int kg  = i & 7;
            uint32_t off = (uint32_t)(row * ROW_F * 4 + kg * 16);
            CP_ASYNC16(abase + off, Asrc + (size_t)row * lda + kg * 4);
            CP_ASYNC16(bbase + off, Bsrc + (size_t)row * ldb + kg * 4);
        }
        CP_ASYNC_COMMIT();
    };

    float acc[4][4][4] = {};
    const int nk = K >> 5;               // >= 8 for all call sites

    load_stage(0, 0);
    load_stage(1, 1);

    for (int ks = 0; ks < nk; ks++) {
        CP_ASYNC_WAIT(1);                // stage ks resident
        __syncthreads();                 // also orders reads of slot (ks-1)%3
        if (ks + 2 < nk) load_stage((ks + 2) % 3, ks + 2);
        else             CP_ASYNC_COMMIT();

        const uint32_t abase = smb + (ks % 3) * STAGE_BYTES;
        const uint32_t bbase = abase + TILE_BYTES;

        #pragma unroll
        for (int k8 = 0; k8 < 32; k8 += 8) {
            uint32_t af[4][4], bf[4][2];
            #pragma unroll
            for (int tm = 0; tm < 4; tm++) {
                LDSM_X4(af[tm][0], af[tm][1], af[tm][2], af[tm][3],
                        abase + a_lo + (uint32_t)(tm * 16 * ROW_F * 4 + k8 * 4));
            }
            #pragma unroll
            for (int tnp = 0; tnp < 2; tnp++) {
                LDSM_X4(bf[2 * tnp][0], bf[2 * tnp][1], bf[2 * tnp + 1][0], bf[2 * tnp + 1][1],
                        bbase + b_lo + (uint32_t)(tnp * 16 * ROW_F * 4 + k8 * 4));
            }
            #pragma unroll
            for (int tm = 0; tm < 4; tm++)
                #pragma unroll
                for (int tn = 0; tn < 4; tn++)
                    mma_tf32(acc[tm][tn], af[tm], bf[tn]);
        }
        // no trailing barrier: slot written next iter == slot whose reads the
        // top-of-iter barrier already ordered (distance 2 mod 3).
    }

    if (TRANSOUT) {
        // proj fusion: out[b, c, n] = acc^T + bias + resid, coalesced along n.
        __syncthreads();                        // stage buffers now free
        float* ws = sm + warp * (64 * 33);      // per-warp 64 rows x 32 cols (pad 33)
        #pragma unroll
        for (int tm = 0; tm < 4; tm++) {
            #pragma unroll
            for (int tn = 0; tn < 4; tn++) {
                const int r  = tm * 16 + g;
                const int cb = tn * 8 + 2 * q;
                float b0 = 0.f, b1 = 0.f;
                if (BIAS) {
                    b0 = __ldg(&bias[n0 + wn * 32 + cb]);
                    b1 = __ldg(&bias[n0 + wn * 32 + cb + 1]);
                }
                ws[r * 33 + cb]           = acc[tm][tn][0] * alpha + b0;
                ws[r * 33 + cb + 1]       = acc[tm][tn][1] * alpha + b1;
                ws[(r + 8) * 33 + cb]     = acc[tm][tn][2] * alpha + b0;
                ws[(r + 8) * 33 + cb + 1] = acc[tm][tn][3] * alpha + b1;
            }
        }
        __syncwarp();
        const int b     = m0 >> 10;                    // batch (tiles never cross)
        const int nbase = (m0 & 1023) + wm * 64;       // n offset of this warp
        #pragma unroll 4
        for (int c = 0; c < 32; c++) {
            const int cg = n0 + wn * 32 + c;
            const size_t o0 = (((size_t)(b * C_ + cg)) << 10) + nbase;
            float v0 = ws[lane * 33 + c]        + resid[o0 + lane];
            float v1 = ws[(lane + 32) * 33 + c] + resid[o0 + 32 + lane];
            Cb[o0 + lane]      = v0;
            Cb[o0 + 32 + lane] = v1;
        }
        return;
    }

    // standard epilogue: (c0,c1)=row g, (c2,c3)=row g+8; cols 2q, 2q+1
    #pragma unroll
    for (int tm = 0; tm < 4; tm++) {
        const int row = m0 + wm * 64 + tm * 16 + g;
        #pragma unroll
        for (int tn = 0; tn < 4; tn++) {
            const int col = n0 + wn * 32 + tn * 8 + 2 * q;
            float b0 = 0.f, b1 = 0.f;
            if (BIAS) { b0 = __ldg(&bias[col]); b1 = __ldg(&bias[col + 1]); }
            float2 v0, v1;
            v0.x = acc[tm][tn][0] * alpha + b0;
            v0.y = acc[tm][tn][1] * alpha + b1;
            v1.x = acc[tm][tn][2] * alpha + b0;
            v1.y = acc[tm][tn][3] * alpha + b1;
            if (round_out) {
                v0.x = round_tf32(v0.x); v0.y = round_tf32(v0.y);
                v1.x = round_tf32(v1.x); v1.y = round_tf32(v1.y);
            }
            *reinterpret_cast<float2*>(&Cb[(size_t)row * ldc + col])       = v0;
            *reinterpret_cast<float2*>(&Cb[(size_t)(row + 8) * ldc + col]) = v1;
        }
    }
}

// ---------------- BN stats ----------------
__global__ void bn_stats_kernel(const float* __restrict__ x) {
    const int c = blockIdx.x, tid = threadIdx.x;
    float s = 0.f, ss = 0.f;
    for (int i = tid; i < B_ * N_; i += 256) {
        int b = i >> 10, p = i & 1023;
        float v = x[(size_t)b * C_ * N_ + (size_t)c * N_ + p];
        s += v; ss += v * v;
    }
    __shared__ float sh1[256], sh2[256];
    sh1[tid] = s; sh2[tid] = ss;
    __syncthreads();
    for (int k = 128; k > 0; k >>= 1) {
        if (tid < k) { sh1[tid] += sh1[tid + k]; sh2[tid] += sh2[tid + k]; }
        __syncthreads();
    }
    if (tid == 0) {
        const float inv_n = 1.0f / (float)(B_ * N_);
        float mean = sh1[0] * inv_n;
        float var  = sh2[0] * inv_n - mean * mean;
        g_mean[c] = mean;
        g_rstd[c] = rsqrtf(var + 1e-5f);
    }
}

// ------- BN apply + transpose [B,C,N] -> [B,N,C], tf32-rounded -----------
__global__ void bn_apply_transpose_kernel(const float* __restrict__ x,
                                          const float* __restrict__ gamma,
                                          const float* __restrict__ beta) {
    __shared__ float sh[32][33];
    const int b = blockIdx.z, c0 = blockIdx.y * 32, n0 = blockIdx.x * 32;
    const int tx = threadIdx.x, ty = threadIdx.y;
    const int c = c0 + ty;
    float v = x[(size_t)b * C_ * N_ + (size_t)c * N_ + (n0 + tx)];
    v = (v - g_mean[c]) * g_rstd[c] * gamma[c] + beta[c];
    sh[ty][tx] = round_tf32(v);
    __syncthreads();
    g_t[((size_t)b * N_ + (n0 + ty)) * C_ + (c0 + tx)] = sh[tx][ty];
}

// ---------------- V transpose: kqv[:, :, 512:768] -> vt [B,C,N] ----------
__global__ void v_transpose_kernel() {
    __shared__ float sh[32][33];
    const int b = blockIdx.z, c0 = blockIdx.y * 32, n0 = blockIdx.x * 32;
    const int tx = threadIdx.x, ty = threadIdx.y;
    sh[ty][tx] = g_kqv[((size_t)b * N_ + (n0 + ty)) * C3_ + 512 + c0 + tx];
    __syncthreads();
    g_vt[((size_t)b * C_ + (c0 + ty)) * N_ + (n0 + tx)] = sh[tx][ty];
}

// ---------------- softmax over rows of 1024 (float4, warp-shuffle) --------
__global__ void softmax_kernel(float* __restrict__ s) {
    const size_t row = blockIdx.x;
    float4* p4 = reinterpret_cast<float4*>(s + row * (size_t)N_);
    const int tid  = threadIdx.x;     // 256 threads, one float4 each
    const int lane = tid & 31;
    const int wid  = tid >> 5;
    __shared__ float sh[8];

    float4 v = p4[tid];
    float mx = fmaxf(fmaxf(v.x, v.y), fmaxf(v.z, v.w));
    #pragma unroll
    for (int o = 16; o > 0; o >>= 1) mx = fmaxf(mx, __shfl_xor_sync(~0u, mx, o));
    if (lane == 0) sh[wid] = mx;
    __syncthreads();
    mx = sh[0];
    #pragma unroll
    for (int w = 1; w < 8; w++) mx = fmaxf(mx, sh[w]);

    v.x = __expf(v.x - mx); v.y = __expf(v.y - mx);
    v.z = __expf(v.z - mx); v.w = __expf(v.w - mx);
    float sum = v.x + v.y + v.z + v.w;
    #pragma unroll
    for (int o = 16; o > 0; o >>= 1) sum += __shfl_xor_sync(~0u, sum, o);
    __syncthreads();
    if (lane == 0) sh[wid] = sum;
    __syncthreads();
    sum = sh[0];
    #pragma unroll
    for (int w = 1; w < 8; w++) sum += sh[w];
    const float inv = 1.0f / sum;

    v.x = round_tf32(v.x * inv); v.y = round_tf32(v.y * inv);
    v.z = round_tf32(v.z * inv); v.w = round_tf32(v.w * inv);
    p4[tid] = v;
}

// ---------------- launch ----------------
extern "C" void kernel_launch(void* const* d_in, const int* in_sizes, int n_in,
                              void* d_out, int out_size) {
    const float* x      = (const float*)d_in[0];
    const float* gamma  = (const float*)d_in[1];
    const float* beta   = (const float*)d_in[2];
    const float* W_kqv  = (const float*)d_in[3];
    const float* b_kqv  = (const float*)d_in[4];
    const float* W_proj = (const float*)d_in[5];
    const float* b_proj = (const float*)d_in[6];
    float* out = (float*)d_out;

    cudaFuncSetAttribute(tc_gemm<true,  false>, cudaFuncAttributeMaxDynamicSharedMemorySize, SMEM_DYN);
    cudaFuncSetAttribute(tc_gemm<false, false>, cudaFuncAttributeMaxDynamicSharedMemorySize, SMEM_DYN);
    cudaFuncSetAttribute(tc_gemm<true,  true >, cudaFuncAttributeMaxDynamicSharedMemorySize, SMEM_DYN);

    void *pt, *pkqv, *ps, *pvt, *po;
    cudaGetSymbolAddress(&pt,   g_t);
    cudaGetSymbolAddress(&pkqv, g_kqv);
    cudaGetSymbolAddress(&ps,   g_s);
    cudaGetSymbolAddress(&pvt,  g_vt);
    cudaGetSymbolAddress(&po,   g_o);
    float* t   = (float*)pt;
    float* kqv = (float*)pkqv;
    float* s   = (float*)ps;
    float* vt  = (float*)pvt;
    float* o   = (float*)po;

    bn_stats_kernel<<<C_, 256>>>(x);
    bn_apply_transpose_kernel<<<dim3(N_ / 32, C_ / 32, B_), dim3(32, 32)>>>(x, gamma, beta);

    // kqv = t @ W_kqv^T + b_kqv (tf32-rounded out)
    tc_gemm<true, false><<<dim3(C3_ / 128, MTOT / 128, 1), 256, SMEM_DYN>>>(
        t, W_kqv, b_kqv, kqv, nullptr, C_, C_, C_, C3_, 0L, 0L, 0L, 1.0f, true);

    // s = q @ k^T / 16 per batch
    tc_gemm<false, false><<<dim3(N_ / 128, N_ / 128, B_), 256, SMEM_DYN>>>(
        kqv, kqv + 256, nullptr, s, nullptr, C_, C3_, C3_, N_,
        (long)N_ * C3_, (long)N_ * C3_, (long)N_ * N_, 0.0625f, false);

    softmax_kernel<<<B_ * N_, 256>>>(s);

    v_transpose_kernel<<<dim3(N_ / 32, C_ / 32, B_), dim3(32, 32)>>>();

    // o = attn @ v : A = s [1024,1024], B = vt [256,1024] (BT), per batch
    tc_gemm<false, false><<<dim3(C_ / 128, N_ / 128, B_), 256, SMEM_DYN>>>(
        s, vt, nullptr, o, nullptr, N_, N_, N_, C_,
        (long)N_ * N_, (long)C_ * N_, (long)N_ * C_, 1.0f, true);

    // fused proj: out[b,c,n] = (o @ W_proj^T + b_proj)^T + x
    tc_gemm<true, true><<<dim3(C_ / 128, MTOT / 128, 1), 256, SMEM_DYN>>>(
        o, W_proj, b_proj, out, x, C_, C_, C_, 0, 0L, 0L, 0L, 1.0f, false);
}

// round 7
// speedup vs baseline: 1.1238x; 1.0676x over previous
#include <cuda_runtime.h>
#include <math.h>
#include <stdint.h>

// ---------------- problem constants ----------------
constexpr int B_   = 32;
constexpr int C_   = 256;
constexpr int N_   = 1024;
constexpr int C3_  = 768;
constexpr int MTOT = B_ * N_;   // 32768

// ---------------- scratch ----------------
__device__ float g_mean[C_];
__device__ float g_rstd[C_];
__device__ float g_t  [(size_t)MTOT * C_];    // [B,N,C]   (tf32-rounded)
__device__ float g_kqv[(size_t)MTOT * C3_];   // [B,N,3C]  (Q,K tf32-rounded; V cols unused)
__device__ float g_s  [(size_t)B_ * N_ * N_]; // [B,N,N]   raw scaled scores
__device__ float g_vt [(size_t)B_ * C_ * N_]; // [B,C,N]   V^T (tf32-rounded)
__device__ float g_o  [(size_t)MTOT * C_];    // [B,N,C]   (tf32-rounded)
__device__ float g_pm [(size_t)B_ * 8 * N_];  // per-tile row max
__device__ float g_pl [(size_t)B_ * 8 * N_];  // per-tile row expsum
__device__ float2 g_ml[(size_t)B_ * N_];      // (rowmax, 1/rowsum)

// ---------------- small PTX helpers ----------------
__device__ __forceinline__ uint32_t smem_u32(const void* p) {
    return (uint32_t)__cvta_generic_to_shared(p);
}
__device__ __forceinline__ float round_tf32(float f) {
    uint32_t r;
    asm("cvt.rna.tf32.f32 %0, %1;" : "=r"(r) : "f"(f));
    return __uint_as_float(r);
}
__device__ __forceinline__ void mma_tf32(float c[4], const uint32_t a[4], const uint32_t b[2]) {
    asm volatile(
        "mma.sync.aligned.m16n8k8.row.col.f32.tf32.tf32.f32 "
        "{%0,%1,%2,%3}, {%4,%5,%6,%7}, {%8,%9}, {%0,%1,%2,%3};"
        : "+f"(c[0]), "+f"(c[1]), "+f"(c[2]), "+f"(c[3])
        : "r"(a[0]), "r"(a[1]), "r"(a[2]), "r"(a[3]), "r"(b[0]), "r"(b[1]));
}
#define LDSM_X4(r0, r1, r2, r3, addr) \
    asm volatile("ldmatrix.sync.aligned.m8n8.x4.shared.b16 {%0,%1,%2,%3}, [%4];" \
        : "=r"(r0), "=r"(r1), "=r"(r2), "=r"(r3) : "r"(addr))
#define CP_ASYNC16(dst, src) \
    asm volatile("cp.async.cg.shared.global [%0], [%1], 16;" :: "r"(dst), "l"(src))
#define CP_ASYNC_COMMIT() asm volatile("cp.async.commit_group;" ::: "memory")
#define CP_ASYNC_WAIT(n)  asm volatile("cp.async.wait_group %0;" :: "n"(n) : "memory")

// ---------------- fused tf32 GEMM family ---------------------------------
// C = alpha * A * B^T; A [M,K] row-major (lda), B [N,K] row-major (ldb).
// CTA 128x128, K-chunk 32, 256 thr = 2(M)x4(N) warps, warp 64x32, ldmatrix.
// 3-stage cp.async pipeline, prefetch distance 2, one barrier per chunk.
// Modes:
//  KQV : +bias; Q/K tiles -> rounded store to kqv; V tiles (n0>=512) ->
//        rounded transposed store to g_vt.
//  QK  : scale by alpha; store raw s; compute per-tile softmax partials.
//  AV  : A-loader applies p = exp(s - m) * inv_l (from g_ml) inline; rounded out.
//  PROJ: +bias; transposed store + residual to final output.
constexpr int MODE_KQV  = 0;
constexpr int MODE_QK   = 1;
constexpr int MODE_AV   = 2;
constexpr int MODE_PROJ = 3;

constexpr int ROW_F       = 36;
constexpr int TILE_FLOATS = 128 * ROW_F;
constexpr int TILE_BYTES  = TILE_FLOATS * 4;
constexpr int STAGE_BYTES = 2 * TILE_BYTES;      // 36864
constexpr int SMEM_DYN    = 3 * STAGE_BYTES;     // 110592 (2 CTAs/SM)

template <int MODE>
__global__ __launch_bounds__(256, 2)
void tc_gemm(const float* __restrict__ A, const float* __restrict__ Bm,
             const float* __restrict__ bias, float* __restrict__ Cm,
             const float* __restrict__ p0,
             int K, int lda, int ldb, int ldc,
             long sA, long sB, long sC, float alpha) {
    extern __shared__ float sm[];

    const int tid  = threadIdx.x;
    const int lane = tid & 31;
    const int warp = tid >> 5;
    const int wm   = warp & 1;
    const int wn   = warp >> 1;
    const int g    = lane >> 2;
    const int q    = lane & 3;

    const int m0 = blockIdx.y * 128;
    const int n0 = blockIdx.x * 128;
    const float* Ab = A  + (size_t)blockIdx.z * sA;
    const float* Bb = Bm + (size_t)blockIdx.z * sB;
    float*       Cb = Cm + (size_t)blockIdx.z * sC;

    const uint32_t smb = smem_u32(sm);

    const uint32_t a_lo =
        (uint32_t)((wm * 64 + (lane & 15)) * ROW_F * 4 + (lane >> 4) * 16);
    const uint32_t b_lo =
        (uint32_t)((wn * 32 + ((lane >> 4) & 1) * 8 + (lane & 7)) * ROW_F * 4 +
                   ((lane >> 3) & 1) * 16);

    // loader: B always cp.async; A cp.async except AV mode
    auto load_stage = [&](int slot, int kc) {
        const uint32_t abase = smb + slot * STAGE_BYTES;
        const uint32_t bbase = abase + TILE_BYTES;
        if (MODE != MODE_AV) {
            const float* Asrc = Ab + (size_t)m0 * lda + kc * 32;
            #pragma unroll
            for (int j = 0; j < 4; j++) {
                int i = tid + j * 256;
                int row = i >> 3, kg = i & 7;
                CP_ASYNC16(abase + (uint32_t)(row * ROW_F * 4 + kg * 16),
                           Asrc + (size_t)row * lda + kg * 4);
            }
        }
        const float* Bsrc = Bb + (size_t)n0 * ldb + kc * 32;
        #pragma unroll
        for (int j = 0; j < 4; j++) {
            int i = tid + j * 256;
            int row = i >> 3, kg = i & 7;
            CP_ASYNC16(bbase + (uint32_t)(row * ROW_F * 4 + kg * 16),
                       Bsrc + (size_t)row * ldb + kg * 4);
        }
        CP_ASYNC_COMMIT();
    };

    // AV: A loaded via LDG, exp-transformed, STS'd
    float4 pend[4];
    float2 mlv[4];
    if (MODE == MODE_AV) {
        #pragma unroll
        for (int j = 0; j < 4; j++) {
            int row = (tid + j * 256) >> 3;
            mlv[j] = g_ml[(size_t)blockIdx.z * N_ + m0 + row];
        }
    }
    auto ldgA = [&](int kc) {
        #pragma unroll
        for (int j = 0; j < 4; j++) {
            int i = tid + j * 256;
            int row = i >> 3, kg = i & 7;
            pend[j] = *reinterpret_cast<const float4*>(
                Ab + (size_t)(m0 + row) * lda + kc * 32 + kg * 4);
        }
    };
    auto stsA = [&](int slot) {
        #pragma unroll
        for (int j = 0; j < 4; j++) {
            int i = tid + j * 256;
            int row = i >> 3, kg = i & 7;
            float4 t = pend[j];
            const float m = mlv[j].x, il = mlv[j].y;
            t.x = round_tf32(__expf(t.x - m) * il);
            t.y = round_tf32(__expf(t.y - m) * il);
            t.z = round_tf32(__expf(t.z - m) * il);
            t.w = round_tf32(__expf(t.w - m) * il);
            *reinterpret_cast<float4*>(
                reinterpret_cast<char*>(sm) + slot * STAGE_BYTES +
                row * ROW_F * 4 + kg * 16) = t;
        }
    };

    float acc[4][4][4] = {};
    const int nk = K >> 5;

    if (MODE == MODE_AV) { ldgA(0); stsA(0); }
    load_stage(0, 0);
    load_stage(1, 1);

    for (int ks = 0; ks < nk; ks++) {
        CP_ASYNC_WAIT(1);
        __syncthreads();
        if (MODE == MODE_AV) { if (ks + 1 < nk) ldgA(ks + 1); }
        if (ks + 2 < nk) load_stage((ks + 2) % 3, ks + 2);
        else             CP_ASYNC_COMMIT();

        const uint32_t abase = smb + (ks % 3) * STAGE_BYTES;
        const uint32_t bbase = abase + TILE_BYTES;

        #pragma unroll
        for (int k8 = 0; k8 < 32; k8 += 8) {
            uint32_t af[4][4], bf[4][2];
            #pragma unroll
            for (int tm = 0; tm < 4; tm++) {
                LDSM_X4(af[tm][0], af[tm][1], af[tm][2], af[tm][3],
                        abase + a_lo + (uint32_t)(tm * 16 * ROW_F * 4 + k8 * 4));
            }
            #pragma unroll
            for (int tnp = 0; tnp < 2; tnp++) {
                LDSM_X4(bf[2 * tnp][0], bf[2 * tnp][1], bf[2 * tnp + 1][0], bf[2 * tnp + 1][1],
                        bbase + b_lo + (uint32_t)(tnp * 16 * ROW_F * 4 + k8 * 4));
            }
            #pragma unroll
            for (int tm = 0; tm < 4; tm++)
                #pragma unroll
                for (int tn = 0; tn < 4; tn++)
                    mma_tf32(acc[tm][tn], af[tm], bf[tn]);
        }
        if (MODE == MODE_AV) { if (ks + 1 < nk) stsA((ks + 1) % 3); }
    }

    // ---------------- epilogues ----------------
    const bool transout = (MODE == MODE_PROJ) || (MODE == MODE_KQV && n0 >= 512);
    if (transout) {
        // out[b, c, n] = acc (+bias) (+resid), coalesced along n
        __syncthreads();
        float* ws = sm + warp * (64 * 33);
        const bool rnd = (MODE == MODE_KQV);
        #pragma unroll
        for (int tm = 0; tm < 4; tm++) {
            #pragma unroll
            for (int tn = 0; tn < 4; tn++) {
                const int r  = tm * 16 + g;
                const int cb = tn * 8 + 2 * q;
                float b0 = __ldg(&bias[n0 + wn * 32 + cb]);
                float b1 = __ldg(&bias[n0 + wn * 32 + cb + 1]);
                float v00 = acc[tm][tn][0] * alpha + b0;
                float v01 = acc[tm][tn][1] * alpha + b1;
                float v10 = acc[tm][tn][2] * alpha + b0;
                float v11 = acc[tm][tn][3] * alpha + b1;
                if (rnd) {
                    v00 = round_tf32(v00); v01 = round_tf32(v01);
                    v10 = round_tf32(v10); v11 = round_tf32(v11);
                }
                ws[r * 33 + cb]           = v00;
                ws[r * 33 + cb + 1]       = v01;
                ws[(r + 8) * 33 + cb]     = v10;
                ws[(r + 8) * 33 + cb + 1] = v11;
            }
        }
        __syncwarp();
        const int b     = m0 >> 10;
        const int nbase = (m0 & 1023) + wm * 64;
        const int cgb   = (MODE == MODE_KQV) ? (n0 - 512) : n0;
        float* outp     = (MODE == MODE_KQV) ? const_cast<float*>(p0) : Cb;
        #pragma unroll 4
        for (int c = 0; c < 32; c++) {
            const int cg = cgb + wn * 32 + c;
            const size_t o0 = (((size_t)(b * C_ + cg)) << 10) + nbase;
            float v0 = ws[lane * 33 + c];
            float v1 = ws[(lane + 32) * 33 + c];
            if (MODE == MODE_PROJ) {
                v0 += p0[o0 + lane];
                v1 += p0[o0 + 32 + lane];
            }
            outp[o0 + lane]      = v0;
            outp[o0 + 32 + lane] = v1;
        }
        return;
    }

    // standard store
    {
        const bool rnd = (MODE == MODE_KQV) || (MODE == MODE_AV);
        #pragma unroll
        for (int tm = 0; tm < 4; tm++) {
            const int row = m0 + wm * 64 + tm * 16 + g;
            #pragma unroll
            for (int tn = 0; tn < 4; tn++) {
                const int col = n0 + wn * 32 + tn * 8 + 2 * q;
                float b0 = 0.f, b1 = 0.f;
                if (MODE == MODE_KQV) { b0 = __ldg(&bias[col]); b1 = __ldg(&bias[col + 1]); }
                float2 v0, v1;
                v0.x = acc[tm][tn][0] * alpha + b0;
                v0.y = acc[tm][tn][1] * alpha + b1;
                v1.x = acc[tm][tn][2] * alpha + b0;
                v1.y = acc[tm][tn][3] * alpha + b1;
                if (rnd) {
                    v0.x = round_tf32(v0.x); v0.y = round_tf32(v0.y);
                    v1.x = round_tf32(v1.x); v1.y = round_tf32(v1.y);
                }
                *reinterpret_cast<float2*>(&Cb[(size_t)row * ldc + col])       = v0;
                *reinterpret_cast<float2*>(&Cb[(size_t)(row + 8) * ldc + col]) = v1;
            }
        }
    }

    if (MODE == MODE_QK) {
        // softmax partials for this 128x128 tile: per-row max + expsum
        float* redm = sm;          // [4][128]
        float* redl = sm + 512;    // [4][128]
        __syncthreads();           // stage buffers free

        // pass 1: per-warp row max (over this warp's 32 cols)
        #pragma unroll
        for (int tm = 0; tm < 4; tm++) {
            float mx0 = -1e30f, mx1 = -1e30f;
            #pragma unroll
            for (int tn = 0; tn < 4; tn++) {
                mx0 = fmaxf(mx0, fmaxf(acc[tm][tn][0], acc[tm][tn][1]));
                mx1 = fmaxf(mx1, fmaxf(acc[tm][tn][2], acc[tm][tn][3]));
            }
            mx0 = fmaxf(mx0, __shfl_xor_sync(~0u, mx0, 1));
            mx0 = fmaxf(mx0, __shfl_xor_sync(~0u, mx0, 2));
            mx1 = fmaxf(mx1, __shfl_xor_sync(~0u, mx1, 1));
            mx1 = fmaxf(mx1, __shfl_xor_sync(~0u, mx1, 2));
            if (q == 0) {
                redm[wn * 128 + wm * 64 + tm * 16 + g]     = mx0 * alpha;
                redm[wn * 128 + wm * 64 + tm * 16 + g + 8] = mx1 * alpha;
            }
        }
        __syncthreads();
        // pass 2: per-warp expsum against the tile-wide row max
        #pragma unroll
        for (int tm = 0; tm < 4; tm++) {
            const int r0 = wm * 64 + tm * 16 + g, r1 = r0 + 8;
            float t0 = fmaxf(fmaxf(redm[r0], redm[128 + r0]),
                             fmaxf(redm[256 + r0], redm[384 + r0]));
            float t1 = fmaxf(fmaxf(redm[r1], redm[128 + r1]),
                             fmaxf(redm[256 + r1], redm[384 + r1]));
            float s0 = 0.f, s1 = 0.f;
            #pragma unroll
            for (int tn = 0; tn < 4; tn++) {
                s0 += __expf(acc[tm][tn][0] * alpha - t0);
                s0 += __expf(acc[tm][tn][1] * alpha - t0);
                s1 += __expf(acc[tm][tn][2] * alpha - t1);
                s1 += __expf(acc[tm][tn][3] * alpha - t1);
            }
            s0 += __shfl_xor_sync(~0u, s0, 1);
            s0 += __shfl_xor_sync(~0u, s0, 2);
            s1 += __shfl_xor_sync(~0u, s1, 1);
            s1 += __shfl_xor_sync(~0u, s1, 2);
            if (q == 0) { redl[wn * 128 + r0] = s0; redl[wn * 128 + r1] = s1; }
        }
        __syncthreads();
        if (tid < 128) {
            float m = fmaxf(fmaxf(redm[tid], redm[128 + tid]),
                            fmaxf(redm[256 + tid], redm[384 + tid]));
            float l = redl[tid] + redl[128 + tid] + redl[256 + tid] + redl[384 + tid];
            const size_t pi = ((size_t)blockIdx.z * 8 + blockIdx.x) * N_ + m0 + tid;
            g_pm[pi] = m;
            g_pl[pi] = l;
        }
    }
}

// ---------------- combine partials -> (rowmax, 1/rowsum) -----------------
__global__ void reduce_ml_kernel() {
    const int idx = blockIdx.x * 256 + threadIdx.x;   // 32768
    const int b = idx >> 10, row = idx & 1023;
    float m = -1e30f;
    #pragma unroll
    for (int t = 0; t < 8; t++)
        m = fmaxf(m, g_pm[((size_t)b * 8 + t) * N_ + row]);
    float l = 0.f;
    #pragma unroll
    for (int t = 0; t < 8; t++) {
        const size_t i = ((size_t)b * 8 + t) * N_ + row;
        l += g_pl[i] * __expf(g_pm[i] - m);
    }
    g_ml[(size_t)b * N_ + row] = make_float2(m, 1.0f / l);
}

// ---------------- BN stats ----------------
__global__ void bn_stats_kernel(const float* __restrict__ x) {
    const int c = blockIdx.x, tid = threadIdx.x;
    float s = 0.f, ss = 0.f;
    for (int i = tid; i < B_ * N_; i += 256) {
        int b = i >> 10, p = i & 1023;
        float v = x[(size_t)b * C_ * N_ + (size_t)c * N_ + p];
        s += v; ss += v * v;
    }
    __shared__ float sh1[256], sh2[256];
    sh1[tid] = s; sh2[tid] = ss;
    __syncthreads();
    for (int k = 128; k > 0; k >>= 1) {
        if (tid < k) { sh1[tid] += sh1[tid + k]; sh2[tid] += sh2[tid + k]; }
        __syncthreads();
    }
    if (tid == 0) {
        const float inv_n = 1.0f / (float)(B_ * N_);
        float mean = sh1[0] * inv_n;
        float var  = sh2[0] * inv_n - mean * mean;
        g_mean[c] = mean;
        g_rstd[c] = rsqrtf(var + 1e-5f);
    }
}

// ------- BN apply + transpose [B,C,N] -> [B,N,C], tf32-rounded -----------
__global__ void bn_apply_transpose_kernel(const float* __restrict__ x,
                                          const float* __restrict__ gamma,
                                          const float* __restrict__ beta) {
    __shared__ float sh[32][33];
    const int b = blockIdx.z, c0 = blockIdx.y * 32, n0 = blockIdx.x * 32;
    const int tx = threadIdx.x, ty = threadIdx.y;
    const int c = c0 + ty;
    float v = x[(size_t)b * C_ * N_ + (size_t)c * N_ + (n0 + tx)];
    v = (v - g_mean[c]) * g_rstd[c] * gamma[c] + beta[c];
    sh[ty][tx] = round_tf32(v);
    __syncthreads();
    g_t[((size_t)b * N_ + (n0 + ty)) * C_ + (c0 + tx)] = sh[tx][ty];
}

// ---------------- launch ----------------
extern "C" void kernel_launch(void* const* d_in, const int* in_sizes, int n_in,
                              void* d_out, int out_size) {
    const float* x      = (const float*)d_in[0];
    const float* gamma  = (const float*)d_in[1];
    const float* beta   = (const float*)d_in[2];
    const float* W_kqv  = (const float*)d_in[3];
    const float* b_kqv  = (const float*)d_in[4];
    const float* W_proj = (const float*)d_in[5];
    const float* b_proj = (const float*)d_in[6];
    float* out = (float*)d_out;

    cudaFuncSetAttribute(tc_gemm<MODE_KQV >, cudaFuncAttributeMaxDynamicSharedMemorySize, SMEM_DYN);
    cudaFuncSetAttribute(tc_gemm<MODE_QK  >, cudaFuncAttributeMaxDynamicSharedMemorySize, SMEM_DYN);
    cudaFuncSetAttribute(tc_gemm<MODE_AV  >, cudaFuncAttributeMaxDynamicSharedMemorySize, SMEM_DYN);
    cudaFuncSetAttribute(tc_gemm<MODE_PROJ>, cudaFuncAttributeMaxDynamicSharedMemorySize, SMEM_DYN);

    void *pt, *pkqv, *ps, *pvt, *po;
    cudaGetSymbolAddress(&pt,   g_t);
    cudaGetSymbolAddress(&pkqv, g_kqv);
    cudaGetSymbolAddress(&ps,   g_s);
    cudaGetSymbolAddress(&pvt,  g_vt);
    cudaGetSymbolAddress(&po,   g_o);
    float* t   = (float*)pt;
    float* kqv = (float*)pkqv;
    float* s   = (float*)ps;
    float* vt  = (float*)pvt;
    float* o   = (float*)po;

    bn_stats_kernel<<<C_, 256>>>(x);
    bn_apply_transpose_kernel<<<dim3(N_ / 32, C_ / 32, B_), dim3(32, 32)>>>(x, gamma, beta);

    // kqv: Q,K -> kqv (rounded); V -> vt transposed (rounded)
    tc_gemm<MODE_KQV><<<dim3(C3_ / 128, MTOT / 128, 1), 256, SMEM_DYN>>>(
        t, W_kqv, b_kqv, kqv, vt, C_, C_, C_, C3_, 0L, 0L, 0L, 1.0f);

    // s = q @ k^T / 16 per batch + softmax partials
    tc_gemm<MODE_QK><<<dim3(N_ / 128, N_ / 128, B_), 256, SMEM_DYN>>>(
        kqv, kqv + 256, nullptr, s, nullptr, C_, C3_, C3_, N_,
        (long)N_ * C3_, (long)N_ * C3_, (long)N_ * N_, 0.0625f);

    reduce_ml_kernel<<<MTOT / 256, 256>>>();

    // o = softmax(s) @ v : exp applied in A-loader; B = vt
    tc_gemm<MODE_AV><<<dim3(C_ / 128, N_ / 128, B_), 256, SMEM_DYN>>>(
        s, vt, nullptr, o, nullptr, N_, N_, N_, C_,
        (long)N_ * N_, (long)C_ * N_, (long)N_ * C_, 1.0f);

    // fused proj: out[b,c,n] = (o @ W_proj^T + b_proj)^T + x
    tc_gemm<MODE_PROJ><<<dim3(C_ / 128, MTOT / 128, 1), 256, SMEM_DYN>>>(
        o, W_proj, b_proj, out, x, C_, C_, C_, 0, 0L, 0L, 0L, 1.0f);
}

// round 8
// speedup vs baseline: 1.1582x; 1.0307x over previous
#include <cuda_runtime.h>
#include <math.h>
#include <stdint.h>

// ---------------- problem constants ----------------
constexpr int B_   = 32;
constexpr int C_   = 256;
constexpr int N_   = 1024;
constexpr int C3_  = 768;
constexpr int MTOT = B_ * N_;   // 32768

// ---------------- scratch ----------------
__device__ float g_mean[C_];
__device__ float g_rstd[C_];
__device__ float g_t  [(size_t)MTOT * C_];    // [B,N,C]   (tf32-rounded)
__device__ float g_kqv[(size_t)MTOT * C3_];   // [B,N,3C]  (Q,K tf32-rounded)
__device__ float g_s  [(size_t)B_ * N_ * N_]; // [B,N,N]   raw scaled scores
__device__ float g_vt [(size_t)B_ * C_ * N_]; // [B,C,N]   V^T (tf32-rounded)
__device__ float g_o  [(size_t)MTOT * C_];    // [B,N,C]   (tf32-rounded)
__device__ float g_pm [(size_t)B_ * 8 * N_];  // per-tile row max
__device__ float g_pl [(size_t)B_ * 8 * N_];  // per-tile row expsum
__device__ float2 g_ml[(size_t)B_ * N_];      // (rowmax, 1/rowsum)

// ---------------- small PTX helpers ----------------
__device__ __forceinline__ uint32_t smem_u32(const void* p) {
    return (uint32_t)__cvta_generic_to_shared(p);
}
__device__ __forceinline__ float round_tf32(float f) {
    uint32_t r;
    asm("cvt.rna.tf32.f32 %0, %1;" : "=r"(r) : "f"(f));
    return __uint_as_float(r);
}
__device__ __forceinline__ void mma_tf32(float c[4], const uint32_t a[4], const uint32_t b[2]) {
    asm volatile(
        "mma.sync.aligned.m16n8k8.row.col.f32.tf32.tf32.f32 "
        "{%0,%1,%2,%3}, {%4,%5,%6,%7}, {%8,%9}, {%0,%1,%2,%3};"
        : "+f"(c[0]), "+f"(c[1]), "+f"(c[2]), "+f"(c[3])
        : "r"(a[0]), "r"(a[1]), "r"(a[2]), "r"(a[3]), "r"(b[0]), "r"(b[1]));
}
#define LDSM_X4(r0, r1, r2, r3, addr) \
    asm volatile("ldmatrix.sync.aligned.m8n8.x4.shared.b16 {%0,%1,%2,%3}, [%4];" \
        : "=r"(r0), "=r"(r1), "=r"(r2), "=r"(r3) : "r"(addr))
#define CP_ASYNC16(dst, src) \
    asm volatile("cp.async.cg.shared.global [%0], [%1], 16;" :: "r"(dst), "l"(src))
#define CP_ASYNC_COMMIT() asm volatile("cp.async.commit_group;" ::: "memory")
#define CP_ASYNC_WAIT(n)  asm volatile("cp.async.wait_group %0;" :: "n"(n) : "memory")

// ---------------- fused tf32 GEMM family ---------------------------------
// C = alpha * A * B^T; A [M,K] row-major (lda), B [N,K] row-major (ldb).
// CTA 128x128, K-chunk 32, 128 thr = 2(M)x2(N) warps, warp tile 64x64,
// 4x8 m16n8k8 MMAs per k8-step. 3-stage cp.async pipe, distance 2, 1 barrier.
constexpr int MODE_KQV  = 0;
constexpr int MODE_QK   = 1;
constexpr int MODE_AV   = 2;
constexpr int MODE_PROJ = 3;

constexpr int NT          = 128;                 // threads per CTA
constexpr int ROW_F       = 36;
constexpr int TILE_FLOATS = 128 * ROW_F;
constexpr int TILE_BYTES  = TILE_FLOATS * 4;
constexpr int STAGE_BYTES = 2 * TILE_BYTES;      // 36864
constexpr int SMEM_DYN    = 3 * STAGE_BYTES;     // 110592 (2 CTAs/SM)

template <int MODE>
__global__ __launch_bounds__(NT, 2)
void tc_gemm(const float* __restrict__ A, const float* __restrict__ Bm,
             const float* __restrict__ bias, float* __restrict__ Cm,
             const float* __restrict__ p0,
             int K, int lda, int ldb, int ldc,
             long sA, long sB, long sC, float alpha) {
    extern __shared__ float sm[];

    const int tid  = threadIdx.x;
    const int lane = tid & 31;
    const int warp = tid >> 5;          // 0..3
    const int wm   = warp & 1;          // M half
    const int wn   = warp >> 1;         // N half
    const int g    = lane >> 2;
    const int q    = lane & 3;

    const int m0 = blockIdx.y * 128;
    const int n0 = blockIdx.x * 128;
    const float* Ab = A  + (size_t)blockIdx.z * sA;
    const float* Bb = Bm + (size_t)blockIdx.z * sB;
    float*       Cb = Cm + (size_t)blockIdx.z * sC;

    const uint32_t smb = smem_u32(sm);

    const uint32_t a_lo =
        (uint32_t)((wm * 64 + (lane & 15)) * ROW_F * 4 + (lane >> 4) * 16);
    const uint32_t b_lo =
        (uint32_t)((wn * 64 + ((lane >> 4) & 1) * 8 + (lane & 7)) * ROW_F * 4 +
                   ((lane >> 3) & 1) * 16);

    auto load_stage = [&](int slot, int kc) {
        const uint32_t abase = smb + slot * STAGE_BYTES;
        const uint32_t bbase = abase + TILE_BYTES;
        if (MODE != MODE_AV) {
            const float* Asrc = Ab + (size_t)m0 * lda + kc * 32;
            #pragma unroll
            for (int j = 0; j < 8; j++) {
                int i = tid + j * NT;
                int row = i >> 3, kg = i & 7;
                CP_ASYNC16(abase + (uint32_t)(row * ROW_F * 4 + kg * 16),
                           Asrc + (size_t)row * lda + kg * 4);
            }
        }
        const float* Bsrc = Bb + (size_t)n0 * ldb + kc * 32;
        #pragma unroll
        for (int j = 0; j < 8; j++) {
            int i = tid + j * NT;
            int row = i >> 3, kg = i & 7;
            CP_ASYNC16(bbase + (uint32_t)(row * ROW_F * 4 + kg * 16),
                       Bsrc + (size_t)row * ldb + kg * 4);
        }
        CP_ASYNC_COMMIT();
    };

    // AV: A (probs) via LDG + exp + STS
    float4 pend[8];
    float2 mlv[8];
    if (MODE == MODE_AV) {
        #pragma unroll
        for (int j = 0; j < 8; j++) {
            int row = (tid + j * NT) >> 3;
            mlv[j] = g_ml[(size_t)blockIdx.z * N_ + m0 + row];
        }
    }
    auto ldgA = [&](int kc) {
        #pragma unroll
        for (int j = 0; j < 8; j++) {
            int i = tid + j * NT;
            int row = i >> 3, kg = i & 7;
            pend[j] = *reinterpret_cast<const float4*>(
                Ab + (size_t)(m0 + row) * lda + kc * 32 + kg * 4);
        }
    };
    auto stsA = [&](int slot) {
        #pragma unroll
        for (int j = 0; j < 8; j++) {
            int i = tid + j * NT;
            int row = i >> 3, kg = i & 7;
            float4 t = pend[j];
            const float m = mlv[j].x, il = mlv[j].y;
            t.x = round_tf32(__expf(t.x - m) * il);
            t.y = round_tf32(__expf(t.y - m) * il);
            t.z = round_tf32(__expf(t.z - m) * il);
            t.w = round_tf32(__expf(t.w - m) * il);
            *reinterpret_cast<float4*>(
                reinterpret_cast<char*>(sm) + slot * STAGE_BYTES +
                row * ROW_F * 4 + kg * 16) = t;
        }
    };

    float acc[4][8][4] = {};
    const int nk = K >> 5;

    if (MODE == MODE_AV) { ldgA(0); stsA(0); }
    load_stage(0, 0);
    load_stage(1, 1);

    for (int ks = 0; ks < nk; ks++) {
        CP_ASYNC_WAIT(1);
        __syncthreads();
        if (MODE == MODE_AV) { if (ks + 1 < nk) ldgA(ks + 1); }
        if (ks + 2 < nk) load_stage((ks + 2) % 3, ks + 2);
        else             CP_ASYNC_COMMIT();

        const uint32_t abase = smb + (ks % 3) * STAGE_BYTES;
        const uint32_t bbase = abase + TILE_BYTES;

        #pragma unroll
        for (int k8 = 0; k8 < 32; k8 += 8) {
            uint32_t af[4][4], bf[8][2];
            #pragma unroll
            for (int tm = 0; tm < 4; tm++) {
                LDSM_X4(af[tm][0], af[tm][1], af[tm][2], af[tm][3],
                        abase + a_lo + (uint32_t)(tm * 16 * ROW_F * 4 + k8 * 4));
            }
            #pragma unroll
            for (int tnp = 0; tnp < 4; tnp++) {
                LDSM_X4(bf[2 * tnp][0], bf[2 * tnp][1], bf[2 * tnp + 1][0], bf[2 * tnp + 1][1],
                        bbase + b_lo + (uint32_t)(tnp * 16 * ROW_F * 4 + k8 * 4));
            }
            #pragma unroll
            for (int tm = 0; tm < 4; tm++)
                #pragma unroll
                for (int tn = 0; tn < 8; tn++)
                    mma_tf32(acc[tm][tn], af[tm], bf[tn]);
        }
        if (MODE == MODE_AV) { if (ks + 1 < nk) stsA((ks + 1) % 3); }
    }

    // ---------------- epilogues ----------------
    const bool transout = (MODE == MODE_PROJ) || (MODE == MODE_KQV && n0 >= 512);
    if (transout) {
        __syncthreads();
        float* ws = sm + warp * (64 * 65);      // 64 rows x 64 cols (pad 65)
        const bool rnd = (MODE == MODE_KQV);
        #pragma unroll
        for (int tm = 0; tm < 4; tm++) {
            #pragma unroll
            for (int tn = 0; tn < 8; tn++) {
                const int r  = tm * 16 + g;
                const int cb = tn * 8 + 2 * q;
                float b0 = __ldg(&bias[n0 + wn * 64 + cb]);
                float b1 = __ldg(&bias[n0 + wn * 64 + cb + 1]);
                float v00 = acc[tm][tn][0] * alpha + b0;
                float v01 = acc[tm][tn][1] * alpha + b1;
                float v10 = acc[tm][tn][2] * alpha + b0;
                float v11 = acc[tm][tn][3] * alpha + b1;
                if (rnd) {
                    v00 = round_tf32(v00); v01 = round_tf32(v01);
                    v10 = round_tf32(v10); v11 = round_tf32(v11);
                }
                ws[r * 65 + cb]           = v00;
                ws[r * 65 + cb + 1]       = v01;
                ws[(r + 8) * 65 + cb]     = v10;
                ws[(r + 8) * 65 + cb + 1] = v11;
            }
        }
        __syncwarp();
        const int b     = m0 >> 10;
        const int nbase = (m0 & 1023) + wm * 64;
        const int cgb   = (MODE == MODE_KQV) ? (n0 - 512) : n0;
        float* outp     = (MODE == MODE_KQV) ? const_cast<float*>(p0) : Cb;
        #pragma unroll 4
        for (int c = 0; c < 64; c++) {
            const int cg = cgb + wn * 64 + c;
            const size_t o0 = (((size_t)(b * C_ + cg)) << 10) + nbase;
            float v0 = ws[lane * 65 + c];
            float v1 = ws[(lane + 32) * 65 + c];
            if (MODE == MODE_PROJ) {
                v0 += p0[o0 + lane];
                v1 += p0[o0 + 32 + lane];
            }
            outp[o0 + lane]      = v0;
            outp[o0 + 32 + lane] = v1;
        }
        return;
    }

    // standard store
    {
        const bool rnd = (MODE == MODE_KQV) || (MODE == MODE_AV);
        #pragma unroll
        for (int tm = 0; tm < 4; tm++) {
            const int row = m0 + wm * 64 + tm * 16 + g;
            #pragma unroll
            for (int tn = 0; tn < 8; tn++) {
                const int col = n0 + wn * 64 + tn * 8 + 2 * q;
                float b0 = 0.f, b1 = 0.f;
                if (MODE == MODE_KQV) { b0 = __ldg(&bias[col]); b1 = __ldg(&bias[col + 1]); }
                float2 v0, v1;
                v0.x = acc[tm][tn][0] * alpha + b0;
                v0.y = acc[tm][tn][1] * alpha + b1;
                v1.x = acc[tm][tn][2] * alpha + b0;
                v1.y = acc[tm][tn][3] * alpha + b1;
                if (rnd) {
                    v0.x = round_tf32(v0.x); v0.y = round_tf32(v0.y);
                    v1.x = round_tf32(v1.x); v1.y = round_tf32(v1.y);
                }
                *reinterpret_cast<float2*>(&Cb[(size_t)row * ldc + col])       = v0;
                *reinterpret_cast<float2*>(&Cb[(size_t)(row + 8) * ldc + col]) = v1;
            }
        }
    }

    if (MODE == MODE_QK) {
        // softmax partials: per-row max + expsum over this 128-col tile
        float* redm = sm;          // [2][128]
        float* redl = sm + 256;    // [2][128]
        __syncthreads();

        #pragma unroll
        for (int tm = 0; tm < 4; tm++) {
            float mx0 = -1e30f, mx1 = -1e30f;
            #pragma unroll
            for (int tn = 0; tn < 8; tn++) {
                mx0 = fmaxf(mx0, fmaxf(acc[tm][tn][0], acc[tm][tn][1]));
                mx1 = fmaxf(mx1, fmaxf(acc[tm][tn][2], acc[tm][tn][3]));
            }
            mx0 = fmaxf(mx0, __shfl_xor_sync(~0u, mx0, 1));
            mx0 = fmaxf(mx0, __shfl_xor_sync(~0u, mx0, 2));
            mx1 = fmaxf(mx1, __shfl_xor_sync(~0u, mx1, 1));
            mx1 = fmaxf(mx1, __shfl_xor_sync(~0u, mx1, 2));
            if (q == 0) {
                redm[wn * 128 + wm * 64 + tm * 16 + g]     = mx0 * alpha;
                redm[wn * 128 + wm * 64 + tm * 16 + g + 8] = mx1 * alpha;
            }
        }
        __syncthreads();
        #pragma unroll
        for (int tm = 0; tm < 4; tm++) {
            const int r0 = wm * 64 + tm * 16 + g, r1 = r0 + 8;
            float t0 = fmaxf(redm[r0], redm[128 + r0]);
            float t1 = fmaxf(redm[r1], redm[128 + r1]);
            float s0 = 0.f, s1 = 0.f;
            #pragma unroll
            for (int tn = 0; tn < 8; tn++) {
                s0 += __expf(acc[tm][tn][0] * alpha - t0);
                s0 += __expf(acc[tm][tn][1] * alpha - t0);
                s1 += __expf(acc[tm][tn][2] * alpha - t1);
                s1 += __expf(acc[tm][tn][3] * alpha - t1);
            }
            s0 += __shfl_xor_sync(~0u, s0, 1);
            s0 += __shfl_xor_sync(~0u, s0, 2);
            s1 += __shfl_xor_sync(~0u, s1, 1);
            s1 += __shfl_xor_sync(~0u, s1, 2);
            if (q == 0) { redl[wn * 128 + r0] = s0; redl[wn * 128 + r1] = s1; }
        }
        __syncthreads();
        if (tid < 128) {
            float m = fmaxf(redm[tid], redm[128 + tid]);
            float l = redl[tid] + redl[128 + tid];
            const size_t pi = ((size_t)blockIdx.z * 8 + blockIdx.x) * N_ + m0 + tid;
            g_pm[pi] = m;
            g_pl[pi] = l;
        }
    }
}

// ---------------- combine partials -> (rowmax, 1/rowsum) -----------------
__global__ void reduce_ml_kernel() {
    const int idx = blockIdx.x * 256 + threadIdx.x;   // 32768
    const int b = idx >> 10, row = idx & 1023;
    float m = -1e30f;
    #pragma unroll
    for (int t = 0; t < 8; t++)
        m = fmaxf(m, g_pm[((size_t)b * 8 + t) * N_ + row]);
    float l = 0.f;
    #pragma unroll
    for (int t = 0; t < 8; t++) {
        const size_t i = ((size_t)b * 8 + t) * N_ + row;
        l += g_pl[i] * __expf(g_pm[i] - m);
    }
    g_ml[(size_t)b * N_ + row] = make_float2(m, 1.0f / l);
}

// ---------------- BN stats ----------------
__global__ void bn_stats_kernel(const float* __restrict__ x) {
    const int c = blockIdx.x, tid = threadIdx.x;
    float s = 0.f, ss = 0.f;
    for (int i = tid; i < B_ * N_; i += 256) {
        int b = i >> 10, p = i & 1023;
        float v = x[(size_t)b * C_ * N_ + (size_t)c * N_ + p];
        s += v; ss += v * v;
    }
    __shared__ float sh1[256], sh2[256];
    sh1[tid] = s; sh2[tid] = ss;
    __syncthreads();
    for (int k = 128; k > 0; k >>= 1) {
        if (tid < k) { sh1[tid] += sh1[tid + k]; sh2[tid] += sh2[tid + k]; }
        __syncthreads();
    }
    if (tid == 0) {
        const float inv_n = 1.0f / (float)(B_ * N_);
        float mean = sh1[0] * inv_n;
        float var  = sh2[0] * inv_n - mean * mean;
        g_mean[c] = mean;
        g_rstd[c] = rsqrtf(var + 1e-5f);
    }
}

// ------- BN apply + transpose [B,C,N] -> [B,N,C], tf32-rounded -----------
__global__ void bn_apply_transpose_kernel(const float* __restrict__ x,
                                          const float* __restrict__ gamma,
                                          const float* __restrict__ beta) {
    __shared__ float sh[32][33];
    const int b = blockIdx.z, c0 = blockIdx.y * 32, n0 = blockIdx.x * 32;
    const int tx = threadIdx.x, ty = threadIdx.y;
    const int c = c0 + ty;
    float v = x[(size_t)b * C_ * N_ + (size_t)c * N_ + (n0 + tx)];
    v = (v - g_mean[c]) * g_rstd[c] * gamma[c] + beta[c];
    sh[ty][tx] = round_tf32(v);
    __syncthreads();
    g_t[((size_t)b * N_ + (n0 + ty)) * C_ + (c0 + tx)] = sh[tx][ty];
}

// ---------------- launch ----------------
extern "C" void kernel_launch(void* const* d_in, const int* in_sizes, int n_in,
                              void* d_out, int out_size) {
    const float* x      = (const float*)d_in[0];
    const float* gamma  = (const float*)d_in[1];
    const float* beta   = (const float*)d_in[2];
    const float* W_kqv  = (const float*)d_in[3];
    const float* b_kqv  = (const float*)d_in[4];
    const float* W_proj = (const float*)d_in[5];
    const float* b_proj = (const float*)d_in[6];
    float* out = (float*)d_out;

    cudaFuncSetAttribute(tc_gemm<MODE_KQV >, cudaFuncAttributeMaxDynamicSharedMemorySize, SMEM_DYN);
    cudaFuncSetAttribute(tc_gemm<MODE_QK  >, cudaFuncAttributeMaxDynamicSharedMemorySize, SMEM_DYN);
    cudaFuncSetAttribute(tc_gemm<MODE_AV  >, cudaFuncAttributeMaxDynamicSharedMemorySize, SMEM_DYN);
    cudaFuncSetAttribute(tc_gemm<MODE_PROJ>, cudaFuncAttributeMaxDynamicSharedMemorySize, SMEM_DYN);

    void *pt, *pkqv, *ps, *pvt, *po;
    cudaGetSymbolAddress(&pt,   g_t);
    cudaGetSymbolAddress(&pkqv, g_kqv);
    cudaGetSymbolAddress(&ps,   g_s);
    cudaGetSymbolAddress(&pvt,  g_vt);
    cudaGetSymbolAddress(&po,   g_o);
    float* t   = (float*)pt;
    float* kqv = (float*)pkqv;
    float* s   = (float*)ps;
    float* vt  = (float*)pvt;
    float* o   = (float*)po;

    bn_stats_kernel<<<C_, 256>>>(x);
    bn_apply_transpose_kernel<<<dim3(N_ / 32, C_ / 32, B_), dim3(32, 32)>>>(x, gamma, beta);

    // kqv: Q,K -> kqv (rounded); V -> vt transposed (rounded)
    tc_gemm<MODE_KQV><<<dim3(C3_ / 128, MTOT / 128, 1), NT, SMEM_DYN>>>(
        t, W_kqv, b_kqv, kqv, vt, C_, C_, C_, C3_, 0L, 0L, 0L, 1.0f);

    // s = q @ k^T / 16 per batch + softmax partials
    tc_gemm<MODE_QK><<<dim3(N_ / 128, N_ / 128, B_), NT, SMEM_DYN>>>(
        kqv, kqv + 256, nullptr, s, nullptr, C_, C3_, C3_, N_,
        (long)N_ * C3_, (long)N_ * C3_, (long)N_ * N_, 0.0625f);

    reduce_ml_kernel<<<MTOT / 256, 256>>>();

    // o = softmax(s) @ v : exp applied in A-loader; B = vt
    tc_gemm<MODE_AV><<<dim3(C_ / 128, N_ / 128, B_), NT, SMEM_DYN>>>(
        s, vt, nullptr, o, nullptr, N_, N_, N_, C_,
        (long)N_ * N_, (long)C_ * N_, (long)N_ * C_, 1.0f);

    // fused proj: out[b,c,n] = (o @ W_proj^T + b_proj)^T + x
    tc_gemm<MODE_PROJ><<<dim3(C_ / 128, MTOT / 128, 1), NT, SMEM_DYN>>>(
        o, W_proj, b_proj, out, x, C_, C_, C_, 0, 0L, 0L, 0L, 1.0f);
}

// round 9
// speedup vs baseline: 1.7509x; 1.5117x over previous
#include <cuda_runtime.h>
#include <cuda_fp16.h>
#include <math.h>
#include <stdint.h>

// ---------------- problem constants ----------------
constexpr int B_   = 32;
constexpr int C_   = 256;
constexpr int N_   = 1024;
constexpr int C3_  = 768;
constexpr int MTOT = B_ * N_;   // 32768

// ---------------- scratch (half intermediates) ----------------
__device__ float  g_mean[C_];
__device__ float  g_rstd[C_];
__device__ __half g_t  [(size_t)MTOT * C_];    // [B,N,C]
__device__ __half g_kqv[(size_t)MTOT * C3_];   // [B,N,3C] (Q,K used)
__device__ __half g_s  [(size_t)B_ * N_ * N_]; // [B,N,N] scaled scores
__device__ __half g_vt [(size_t)B_ * C_ * N_]; // [B,C,N] V^T
__device__ __half g_o  [(size_t)MTOT * C_];    // [B,N,C]
__device__ __half g_wk [(size_t)C3_ * C_];     // W_kqv fp16
__device__ __half g_wp [(size_t)C_ * C_];      // W_proj fp16
__device__ float  g_pm [(size_t)B_ * 8 * N_];  // per-tile row max
__device__ float  g_pl [(size_t)B_ * 8 * N_];  // per-tile row expsum
__device__ float2 g_ml [(size_t)B_ * N_];      // (rowmax, 1/rowsum)

// ---------------- PTX helpers ----------------
__device__ __forceinline__ uint32_t smem_u32(const void* p) {
    return (uint32_t)__cvta_generic_to_shared(p);
}
__device__ __forceinline__ void mma_fp16(float c[4], const uint32_t a[4], const uint32_t b[2]) {
    asm volatile(
        "mma.sync.aligned.m16n8k16.row.col.f32.f16.f16.f32 "
        "{%0,%1,%2,%3}, {%4,%5,%6,%7}, {%8,%9}, {%0,%1,%2,%3};"
        : "+f"(c[0]), "+f"(c[1]), "+f"(c[2]), "+f"(c[3])
        : "r"(a[0]), "r"(a[1]), "r"(a[2]), "r"(a[3]), "r"(b[0]), "r"(b[1]));
}
#define LDSM_X4(r0, r1, r2, r3, addr) \
    asm volatile("ldmatrix.sync.aligned.m8n8.x4.shared.b16 {%0,%1,%2,%3}, [%4];" \
        : "=r"(r0), "=r"(r1), "=r"(r2), "=r"(r3) : "r"(addr))
#define CP_ASYNC16(dst, src) \
    asm volatile("cp.async.cg.shared.global [%0], [%1], 16;" :: "r"(dst), "l"(src))
#define CP_ASYNC_COMMIT() asm volatile("cp.async.commit_group;" ::: "memory")
#define CP_ASYNC_WAIT(n)  asm volatile("cp.async.wait_group %0;" :: "n"(n) : "memory")

// ---------------- fused fp16 GEMM family (fp32 accumulate) ----------------
constexpr int MODE_KQV  = 0;
constexpr int MODE_QK   = 1;
constexpr int MODE_AV   = 2;
constexpr int MODE_PROJ = 3;

constexpr int NT          = 256;
constexpr int ROW_B       = 144;                 // padded row stride (bytes)
constexpr int TILE_BYTES  = 128 * ROW_B;         // 18432
constexpr int STAGE_BYTES = 2 * TILE_BYTES;      // 36864
constexpr int SMEM_DYN    = 3 * STAGE_BYTES;     // 110592 (2 CTAs/SM)

template <int MODE>
__global__ __launch_bounds__(NT, 2)
void tc_gemm(const __half* __restrict__ A, const __half* __restrict__ Bm,
             const float* __restrict__ bias, void* __restrict__ Cm,
             const void* __restrict__ P0,
             int K, int lda, int ldb, int ldc,
             long sA, long sB, long sC, float alpha) {
    extern __shared__ float sm[];

    const int tid  = threadIdx.x;
    const int lane = tid & 31;
    const int warp = tid >> 5;
    const int wm   = warp & 1;          // 0..1 (M)
    const int wn   = warp >> 1;         // 0..3 (N)
    const int g    = lane >> 2;
    const int q    = lane & 3;

    const int m0 = blockIdx.y * 128;
    const int n0 = blockIdx.x * 128;
    const __half* Ab = A  + (size_t)blockIdx.z * sA;
    const __half* Bb = Bm + (size_t)blockIdx.z * sB;

    const uint32_t smb = smem_u32(sm);

    const uint32_t a_lo =
        (uint32_t)((wm * 64 + (lane & 15)) * ROW_B + (lane >> 4) * 16);
    const uint32_t b_lo =
        (uint32_t)((wn * 32 + ((lane >> 4) & 1) * 8 + (lane & 7)) * ROW_B +
                   ((lane >> 3) & 1) * 16);

    auto load_stage = [&](int slot, int kc) {
        const uint32_t abase = smb + slot * STAGE_BYTES;
        const uint32_t bbase = abase + TILE_BYTES;
        if (MODE != MODE_AV) {
            const __half* Asrc = Ab + (size_t)m0 * lda + kc * 64;
            #pragma unroll
            for (int j = 0; j < 4; j++) {
                int i = tid + j * NT;
                int row = i >> 3, kg = i & 7;
                CP_ASYNC16(abase + (uint32_t)(row * ROW_B + kg * 16),
                           Asrc + (size_t)row * lda + kg * 8);
            }
        }
        const __half* Bsrc = Bb + (size_t)n0 * ldb + kc * 64;
        #pragma unroll
        for (int j = 0; j < 4; j++) {
            int i = tid + j * NT;
            int row = i >> 3, kg = i & 7;
            CP_ASYNC16(bbase + (uint32_t)(row * ROW_B + kg * 16),
                       Bsrc + (size_t)row * ldb + kg * 8);
        }
        CP_ASYNC_COMMIT();
    };

    // AV: A (scores) via LDG -> exp -> half -> STS
    uint4  pend[4];
    float2 mlv[4];
    if (MODE == MODE_AV) {
        #pragma unroll
        for (int j = 0; j < 4; j++) {
            int row = (tid + j * NT) >> 3;
            mlv[j] = g_ml[(size_t)blockIdx.z * N_ + m0 + row];
        }
    }
    auto ldgA = [&](int kc) {
        #pragma unroll
        for (int j = 0; j < 4; j++) {
            int i = tid + j * NT;
            int row = i >> 3, kg = i & 7;
            pend[j] = *reinterpret_cast<const uint4*>(
                Ab + (size_t)(m0 + row) * lda + kc * 64 + kg * 8);
        }
    };
    auto stsA = [&](int slot) {
        #pragma unroll
        for (int j = 0; j < 4; j++) {
            int i = tid + j * NT;
            int row = i >> 3, kg = i & 7;
            const float m = mlv[j].x, il = mlv[j].y;
            const __half2* h = reinterpret_cast<const __half2*>(&pend[j]);
            uint4 outv;
            __half2* ho = reinterpret_cast<__half2*>(&outv);
            #pragma unroll
            for (int p = 0; p < 4; p++) {
                float2 f = __half22float2(h[p]);
                f.x = __expf(f.x - m) * il;
                f.y = __expf(f.y - m) * il;
                ho[p] = __float22half2_rn(f);
            }
            *reinterpret_cast<uint4*>(
                reinterpret_cast<char*>(sm) + slot * STAGE_BYTES +
                row * ROW_B + kg * 16) = outv;
        }
    };

    float acc[4][4][4] = {};
    const int nk = K >> 6;               // K-chunks of 64

    if (MODE == MODE_AV) { ldgA(0); stsA(0); }
    load_stage(0, 0);
    load_stage(1, 1);

    for (int ks = 0; ks < nk; ks++) {
        CP_ASYNC_WAIT(1);
        __syncthreads();
        if (MODE == MODE_AV) { if (ks + 1 < nk) ldgA(ks + 1); }
        if (ks + 2 < nk) load_stage((ks + 2) % 3, ks + 2);
        else             CP_ASYNC_COMMIT();

        const uint32_t abase = smb + (ks % 3) * STAGE_BYTES;
        const uint32_t bbase = abase + TILE_BYTES;

        #pragma unroll
        for (int kk = 0; kk < 4; kk++) {
            uint32_t af[4][4], bf[4][2];
            #pragma unroll
            for (int tm = 0; tm < 4; tm++) {
                LDSM_X4(af[tm][0], af[tm][1], af[tm][2], af[tm][3],
                        abase + a_lo + (uint32_t)(tm * 16 * ROW_B + kk * 32));
            }
            #pragma unroll
            for (int tnp = 0; tnp < 2; tnp++) {
                LDSM_X4(bf[2 * tnp][0], bf[2 * tnp][1], bf[2 * tnp + 1][0], bf[2 * tnp + 1][1],
                        bbase + b_lo + (uint32_t)(tnp * 16 * ROW_B + kk * 32));
            }
            #pragma unroll
            for (int tm = 0; tm < 4; tm++)
                #pragma unroll
                for (int tn = 0; tn < 4; tn++)
                    mma_fp16(acc[tm][tn], af[tm], bf[tn]);
        }
        if (MODE == MODE_AV) { if (ks + 1 < nk) stsA((ks + 1) % 3); }
    }

    // ---------------- epilogues ----------------
    const bool transout = (MODE == MODE_PROJ) || (MODE == MODE_KQV && n0 >= 512);
    if (transout) {
        __syncthreads();
        float* ws = sm + warp * (64 * 33);
        #pragma unroll
        for (int tm = 0; tm < 4; tm++) {
            #pragma unroll
            for (int tn = 0; tn < 4; tn++) {
                const int r  = tm * 16 + g;
                const int cb = tn * 8 + 2 * q;
                float b0 = __ldg(&bias[n0 + wn * 32 + cb]);
                float b1 = __ldg(&bias[n0 + wn * 32 + cb + 1]);
                ws[r * 33 + cb]           = acc[tm][tn][0] * alpha + b0;
                ws[r * 33 + cb + 1]       = acc[tm][tn][1] * alpha + b1;
                ws[(r + 8) * 33 + cb]     = acc[tm][tn][2] * alpha + b0;
                ws[(r + 8) * 33 + cb + 1] = acc[tm][tn][3] * alpha + b1;
            }
        }
        __syncwarp();
        const int b     = m0 >> 10;
        const int nbase = (m0 & 1023) + wm * 64;
        #pragma unroll 4
        for (int c = 0; c < 32; c++) {
            float v0 = ws[lane * 33 + c];
            float v1 = ws[(lane + 32) * 33 + c];
            if (MODE == MODE_PROJ) {
                const int cg = n0 + wn * 32 + c;
                const size_t o0 = (((size_t)(b * C_ + cg)) << 10) + nbase;
                const float* xr = (const float*)P0;
                ((float*)Cm)[o0 + lane]      = v0 + xr[o0 + lane];
                ((float*)Cm)[o0 + 32 + lane] = v1 + xr[o0 + 32 + lane];
            } else {
                const int cg = (n0 - 512) + wn * 32 + c;
                const size_t o0 = (((size_t)(b * C_ + cg)) << 10) + nbase;
                g_vt[o0 + lane]      = __float2half_rn(v0);
                g_vt[o0 + 32 + lane] = __float2half_rn(v1);
            }
        }
        return;
    }

    // standard store (half output)
    {
        __half* Cb = (__half*)Cm + (size_t)blockIdx.z * sC;
        #pragma unroll
        for (int tm = 0; tm < 4; tm++) {
            const int row = m0 + wm * 64 + tm * 16 + g;
            #pragma unroll
            for (int tn = 0; tn < 4; tn++) {
                const int col = n0 + wn * 32 + tn * 8 + 2 * q;
                float b0 = 0.f, b1 = 0.f;
                if (MODE == MODE_KQV) { b0 = __ldg(&bias[col]); b1 = __ldg(&bias[col + 1]); }
                __half2 v0 = __floats2half2_rn(acc[tm][tn][0] * alpha + b0,
                                               acc[tm][tn][1] * alpha + b1);
                __half2 v1 = __floats2half2_rn(acc[tm][tn][2] * alpha + b0,
                                               acc[tm][tn][3] * alpha + b1);
                *reinterpret_cast<__half2*>(&Cb[(size_t)row * ldc + col])       = v0;
                *reinterpret_cast<__half2*>(&Cb[(size_t)(row + 8) * ldc + col]) = v1;
            }
        }
    }

    if (MODE == MODE_QK) {
        float* redm = sm;          // [4][128]
        float* redl = sm + 512;    // [4][128]
        __syncthreads();

        #pragma unroll
        for (int tm = 0; tm < 4; tm++) {
            float mx0 = -1e30f, mx1 = -1e30f;
            #pragma unroll
            for (int tn = 0; tn < 4; tn++) {
                mx0 = fmaxf(mx0, fmaxf(acc[tm][tn][0], acc[tm][tn][1]));
                mx1 = fmaxf(mx1, fmaxf(acc[tm][tn][2], acc[tm][tn][3]));
            }
            mx0 = fmaxf(mx0, __shfl_xor_sync(~0u, mx0, 1));
            mx0 = fmaxf(mx0, __shfl_xor_sync(~0u, mx0, 2));
            mx1 = fmaxf(mx1, __shfl_xor_sync(~0u, mx1, 1));
            mx1 = fmaxf(mx1, __shfl_xor_sync(~0u, mx1, 2));
            if (q == 0) {
                redm[wn * 128 + wm * 64 + tm * 16 + g]     = mx0 * alpha;
                redm[wn * 128 + wm * 64 + tm * 16 + g + 8] = mx1 * alpha;
            }
        }
        __syncthreads();
        #pragma unroll
        for (int tm = 0; tm < 4; tm++) {
            const int r0 = wm * 64 + tm * 16 + g, r1 = r0 + 8;
            float t0 = fmaxf(fmaxf(redm[r0], redm[128 + r0]),
                             fmaxf(redm[256 + r0], redm[384 + r0]));
            float t1 = fmaxf(fmaxf(redm[r1], redm[128 + r1]),
                             fmaxf(redm[256 + r1], redm[384 + r1]));
            float s0 = 0.f, s1 = 0.f;
            #pragma unroll
            for (int tn = 0; tn < 4; tn++) {
                s0 += __expf(acc[tm][tn][0] * alpha - t0);
                s0 += __expf(acc[tm][tn][1] * alpha - t0);
                s1 += __expf(acc[tm][tn][2] * alpha - t1);
                s1 += __expf(acc[tm][tn][3] * alpha - t1);
            }
            s0 += __shfl_xor_sync(~0u, s0, 1);
            s0 += __shfl_xor_sync(~0u, s0, 2);
            s1 += __shfl_xor_sync(~0u, s1, 1);
            s1 += __shfl_xor_sync(~0u, s1, 2);
            if (q == 0) { redl[wn * 128 + r0] = s0; redl[wn * 128 + r1] = s1; }
        }
        __syncthreads();
        if (tid < 128) {
            float m = fmaxf(fmaxf(redm[tid], redm[128 + tid]),
                            fmaxf(redm[256 + tid], redm[384 + tid]));
            float l = redl[tid] + redl[128 + tid] + redl[256 + tid] + redl[384 + tid];
            const size_t pi = ((size_t)blockIdx.z * 8 + blockIdx.x) * N_ + m0 + tid;
            g_pm[pi] = m;
            g_pl[pi] = l;
        }
    }
}

// ---------------- combine partials -> (rowmax, 1/rowsum) -----------------
__global__ void reduce_ml_kernel() {
    const int idx = blockIdx.x * 256 + threadIdx.x;
    const int b = idx >> 10, row = idx & 1023;
    float m = -1e30f;
    #pragma unroll
    for (int t = 0; t < 8; t++)
        m = fmaxf(m, g_pm[((size_t)b * 8 + t) * N_ + row]);
    float l = 0.f;
    #pragma unroll
    for (int t = 0; t < 8; t++) {
        const size_t i = ((size_t)b * 8 + t) * N_ + row;
        l += g_pl[i] * __expf(g_pm[i] - m);
    }
    g_ml[(size_t)b * N_ + row] = make_float2(m, 1.0f / l);
}

// ---------------- convert weights to fp16 ----------------
__global__ void cvt_w_kernel(const float* __restrict__ wk, const float* __restrict__ wp) {
    const int i = blockIdx.x * 256 + threadIdx.x;
    if (i < C3_ * C_) g_wk[i] = __float2half_rn(wk[i]);
    if (i < C_ * C_)  g_wp[i] = __float2half_rn(wp[i]);
}

// ---------------- BN stats ----------------
__global__ void bn_stats_kernel(const float* __restrict__ x) {
    const int c = blockIdx.x, tid = threadIdx.x;
    float s = 0.f, ss = 0.f;
    for (int i = tid; i < B_ * N_; i += 256) {
        int b = i >> 10, p = i & 1023;
        float v = x[(size_t)b * C_ * N_ + (size_t)c * N_ + p];
        s += v; ss += v * v;
    }
    __shared__ float sh1[256], sh2[256];
    sh1[tid] = s; sh2[tid] = ss;
    __syncthreads();
    for (int k = 128; k > 0; k >>= 1) {
        if (tid < k) { sh1[tid] += sh1[tid + k]; sh2[tid] += sh2[tid + k]; }
        __syncthreads();
    }
    if (tid == 0) {
        const float inv_n = 1.0f / (float)(B_ * N_);
        float mean = sh1[0] * inv_n;
        float var  = sh2[0] * inv_n - mean * mean;
        g_mean[c] = mean;
        g_rstd[c] = rsqrtf(var + 1e-5f);
    }
}

// ------- BN apply + transpose [B,C,N] -> [B,N,C] (fp16 out) --------------
__global__ void bn_apply_transpose_kernel(const float* __restrict__ x,
                                          const float* __restrict__ gamma,
                                          const float* __restrict__ beta) {
    __shared__ float sh[32][33];
    const int b = blockIdx.z, c0 = blockIdx.y * 32, n0 = blockIdx.x * 32;
    const int tx = threadIdx.x, ty = threadIdx.y;
    const int c = c0 + ty;
    float v = x[(size_t)b * C_ * N_ + (size_t)c * N_ + (n0 + tx)];
    v = (v - g_mean[c]) * g_rstd[c] * gamma[c] + beta[c];
    sh[ty][tx] = v;
    __syncthreads();
    g_t[((size_t)b * N_ + (n0 + ty)) * C_ + (c0 + tx)] = __float2half_rn(sh[tx][ty]);
}

// ---------------- launch ----------------
extern "C" void kernel_launch(void* const* d_in, const int* in_sizes, int n_in,
                              void* d_out, int out_size) {
    const float* x      = (const float*)d_in[0];
    const float* gamma  = (const float*)d_in[1];
    const float* beta   = (const float*)d_in[2];
    const float* W_kqv  = (const float*)d_in[3];
    const float* b_kqv  = (const float*)d_in[4];
    const float* W_proj = (const float*)d_in[5];
    const float* b_proj = (const float*)d_in[6];
    float* out = (float*)d_out;

    cudaFuncSetAttribute(tc_gemm<MODE_KQV >, cudaFuncAttributeMaxDynamicSharedMemorySize, SMEM_DYN);
    cudaFuncSetAttribute(tc_gemm<MODE_QK  >, cudaFuncAttributeMaxDynamicSharedMemorySize, SMEM_DYN);
    cudaFuncSetAttribute(tc_gemm<MODE_AV  >, cudaFuncAttributeMaxDynamicSharedMemorySize, SMEM_DYN);
    cudaFuncSetAttribute(tc_gemm<MODE_PROJ>, cudaFuncAttributeMaxDynamicSharedMemorySize, SMEM_DYN);

    void *pt, *pkqv, *ps, *pvt, *po, *pwk, *pwp;
    cudaGetSymbolAddress(&pt,   g_t);
    cudaGetSymbolAddress(&pkqv, g_kqv);
    cudaGetSymbolAddress(&ps,   g_s);
    cudaGetSymbolAddress(&pvt,  g_vt);
    cudaGetSymbolAddress(&po,   g_o);
    cudaGetSymbolAddress(&pwk,  g_wk);
    cudaGetSymbolAddress(&pwp,  g_wp);
    __half* t   = (__half*)pt;
    __half* kqv = (__half*)pkqv;
    __half* s   = (__half*)ps;
    __half* vt  = (__half*)pvt;
    __half* o   = (__half*)po;
    __half* wk  = (__half*)pwk;
    __half* wp  = (__half*)pwp;
    (void)vt;

    bn_stats_kernel<<<C_, 256>>>(x);
    cvt_w_kernel<<<(C3_ * C_) / 256, 256>>>(W_kqv, W_proj);
    bn_apply_transpose_kernel<<<dim3(N_ / 32, C_ / 32, B_), dim3(32, 32)>>>(x, gamma, beta);

    // kqv: Q,K -> kqv; V tiles -> g_vt (transposed, inside kernel)
    tc_gemm<MODE_KQV><<<dim3(C3_ / 128, MTOT / 128, 1), NT, SMEM_DYN>>>(
        t, wk, b_kqv, kqv, nullptr, C_, C_, C_, C3_, 0L, 0L, 0L, 1.0f);

    // s = q @ k^T / 16 per batch + softmax partials
    tc_gemm<MODE_QK><<<dim3(N_ / 128, N_ / 128, B_), NT, SMEM_DYN>>>(
        kqv, kqv + 256, nullptr, s, nullptr, C_, C3_, C3_, N_,
        (long)N_ * C3_, (long)N_ * C3_, (long)N_ * N_, 0.0625f);

    reduce_ml_kernel<<<MTOT / 256, 256>>>();

    // o = softmax(s) @ v : exp in A-loader; B = vt
    tc_gemm<MODE_AV><<<dim3(C_ / 128, N_ / 128, B_), NT, SMEM_DYN>>>(
        s, vt, nullptr, o, nullptr, N_, N_, N_, C_,
        (long)N_ * N_, (long)C_ * N_, (long)N_ * C_, 1.0f);

    // fused proj: out[b,c,n] = (o @ W_proj^T + b_proj)^T + x
    tc_gemm<MODE_PROJ><<<dim3(C_ / 128, MTOT / 128, 1), NT, SMEM_DYN>>>(
        o, wp, b_proj, out, x, C_, C_, C_, 0, 0L, 0L, 0L, 1.0f);
}